// round 11
// baseline (speedup 1.0000x reference)
#include <cuda_runtime.h>
#include <math.h>
#include <stdint.h>

#define BATCH 8
#define NCH   512     // encoder feats
#define BFT   128     // bottleneck
#define HID   512     // hidden
#define TLEN  3200
#define LAY   24
#define NSRC  2
#define EPSV  1e-8f

// ---------------- scratch (device globals; no allocs allowed) ----------------
__device__ float g_feats[BATCH * BFT * TLEN];   // [b][c][t]
__device__ float g_h    [BATCH * HID * TLEN];
__device__ float g_h2   [BATCH * HID * TLEN];
__device__ float g_skip [BATCH * BFT * TLEN];
__device__ float g_part [BATCH * 512 * 2];      // fixed-slot partials (sum,sumsq)

// transposed weights: per 128-row m-tile, layout [mt][k][ml], ml in 0..127
#define OFF_WC   0
#define OFF_W1   65536
#define OFF_WSK  (OFF_W1  + 24 * 65536)
#define OFF_WRES (OFF_WSK + 24 * 65536)
#define OFF_WO   (OFF_WRES + 24 * 65536)
__device__ float g_Wt[OFF_WO + 8 * 16384];

// per-batch gLN-folded weights (2 slots x 512k x 128m per batch) + corr biases
__device__ float g_Ws  [BATCH * 2 * 65536];     // 4 MB
__device__ float g_corr[BATCH * 2 * 128];

// ---------------- packed f32x2 helpers ----------------
#define FFMA2(acc, a, b) \
    asm("fma.rn.f32x2 %0, %1, %2, %0;" : "+l"(acc) : "l"(a), "l"(b))
#define PACK2(out, lo, hi) \
    asm("mov.b64 %0, {%1, %2};" : "=l"(out) : "r"(__float_as_uint(lo)), "r"(__float_as_uint(hi)))
#define UNPACK2(lo, hi, in) \
    { unsigned int _ulo, _uhi; \
      asm("mov.b64 {%0, %1}, %2;" : "=r"(_ulo), "=r"(_uhi) : "l"(in)); \
      lo = __uint_as_float(_ulo); hi = __uint_as_float(_uhi); }

// ---------------- cp.async ----------------
__device__ __forceinline__ uint32_t smem_u32(const void* p) {
    uint32_t a;
    asm("{ .reg .u64 t; cvta.to.shared.u64 t, %1; cvt.u32.u64 %0, t; }" : "=r"(a) : "l"(p));
    return a;
}
#define CP16(dst, src)  asm volatile("cp.async.cg.shared.global [%0], [%1], 16;" :: "r"(dst), "l"(src))
#define CPCOMMIT()      asm volatile("cp.async.commit_group;")
#define CPWAIT1()       asm volatile("cp.async.wait_group 1;")
#define CPWAIT0()       asm volatile("cp.async.wait_group 0;")

// ---------------- helpers ----------------
__device__ __forceinline__ void block_reduce2(float& s, float& q, float* shs, float* shq) {
    int tid = threadIdx.x;
    shs[tid] = s; shq[tid] = q;
    __syncthreads();
    for (int st = 128; st > 0; st >>= 1) {
        if (tid < st) { shs[tid] += shs[tid + st]; shq[tid] += shq[tid + st]; }
        __syncthreads();
    }
    s = shs[0]; q = shq[0];
}

__device__ __forceinline__ void stats_from_part(int b, int pcount, float denom,
                                                float& mean, float& rstd,
                                                float* shs, float* shq) {
    float s = 0.f, q = 0.f;
    for (int j = threadIdx.x; j < pcount; j += 256) {
        s += g_part[(b * 512 + j) * 2 + 0];
        q += g_part[(b * 512 + j) * 2 + 1];
    }
    block_reduce2(s, q, shs, shq);
    mean = s / denom;
    float var = fmaxf(q / denom - mean * mean, 0.f);
    rstd = rsqrtf(var + EPSV);
}

__global__ void k_zero(float* __restrict__ p, int n4) {
    int i = blockIdx.x * blockDim.x + threadIdx.x;
    if (i < n4) reinterpret_cast<float4*>(p)[i] = make_float4(0.f, 0.f, 0.f, 0.f);
}

// transpose weights: src [Mtot][Ktot] -> g_Wt[dstOff + (mt*Ktot + k)*128 + ml]
__global__ void k_wt(const float* __restrict__ src, int Ktot, size_t dstOff) {
    __shared__ float t[32][33];
    int k0 = blockIdx.x * 32, m0 = blockIdx.y * 32;
    int lx = threadIdx.x & 31, ly = threadIdx.x >> 5;
#pragma unroll
    for (int i = 0; i < 4; i++)
        t[ly + i * 8][lx] = src[(size_t)(m0 + ly + i * 8) * Ktot + k0 + lx];
    __syncthreads();
#pragma unroll
    for (int i = 0; i < 4; i++) {
        int k = k0 + ly + i * 8;
        int m = m0 + lx;
        g_Wt[dstOff + ((size_t)(m >> 7) * Ktot + k) * 128 + (m & 127)] = t[lx][ly + i * 8];
    }
}

// per-row stats for input x [b][c][t]
__global__ void k_rowstats(const float* __restrict__ X) {
    int c = blockIdx.x, b = blockIdx.y;
    const float* p = X + ((size_t)b * NCH + c) * TLEN;
    float s = 0.f, q = 0.f;
    for (int t = threadIdx.x; t < TLEN; t += 256) {
        float v = p[t];
        s += v; q += v * v;
    }
    __shared__ float shs[256], shq[256];
    block_reduce2(s, q, shs, shq);
    if (threadIdx.x == 0) {
        g_part[(b * 512 + c) * 2 + 0] = s;
        g_part[(b * 512 + c) * 2 + 1] = q;
    }
}

// fold gLN affine into weights: g_Ws[b][slot] = Wt(src) * a_k, corr = bias + W . d_k
__global__ void k_scalew(size_t offA, size_t offB,
                         const float* __restrict__ bA, const float* __restrict__ bB,
                         const float* __restrict__ gvec, const float* __restrict__ bvec,
                         int pcount, float denom) {
    __shared__ float shs[256], shq[256];
    int slot = blockIdx.x, b = blockIdx.y;
    float mean, rstd;
    stats_from_part(b, pcount, denom, mean, rstd, shs, shq);
    __syncthreads();
    size_t src = slot ? offB : offA;
    const float* bias = slot ? bB : bA;
    float* dst = g_Ws + ((size_t)(b * 2 + slot)) * 65536;
    int ml = threadIdx.x & 127, kh = threadIdx.x >> 7;
    float corr = 0.f;
    for (int k = kh; k < 512; k += 2) {
        float ac = gvec[k] * rstd;
        float dc = bvec[k] - ac * mean;
        float w = g_Wt[src + (size_t)k * 128 + ml];
        dst[(size_t)k * 128 + ml] = w * ac;
        corr = fmaf(w, dc, corr);
    }
    __syncthreads();
    shs[threadIdx.x] = corr;
    __syncthreads();
    if (kh == 0)
        g_corr[(b * 2 + slot) * 128 + ml] = bias[ml] + shs[ml] + shs[ml + 128];
}

// fused gLN1 + depthwise dilated conv + PReLU + stats
__global__ void k_dw(const float* __restrict__ Wd, const float* __restrict__ bd,
                     const float* __restrict__ g1, const float* __restrict__ be1,
                     const float* __restrict__ a2, int layer, int dil, float denom) {
    __shared__ float shs[256], shq[256];
    int c = blockIdx.x, b = blockIdx.y;
    float mean, rstd;
    stats_from_part(b, 100, denom, mean, rstd, shs, shq);
    __syncthreads();
    int lc = layer * HID + c;
    float ga = g1[lc] * rstd;
    float dd = be1[lc] - ga * mean;
    float w0 = Wd[lc * 3 + 0], w1 = Wd[lc * 3 + 1], w2 = Wd[lc * 3 + 2];
    float bv = bd[lc];
    float al = a2[layer];
    const float* ph = g_h  + ((size_t)b * HID + c) * TLEN;
    float*       po = g_h2 + ((size_t)b * HID + c) * TLEN;
    float s = 0.f, q = 0.f;
    for (int t = threadIdx.x; t < TLEN; t += 256) {
        float ctr = ga * ph[t] + dd;
        float lf  = (t >= dil)        ? ga * ph[t - dil] + dd : 0.f;
        float rt  = (t + dil < TLEN)  ? ga * ph[t + dil] + dd : 0.f;
        float v = fmaf(w0, lf, fmaf(w1, ctr, fmaf(w2, rt, bv)));
        v = (v < 0.f) ? al * v : v;
        po[t] = v;
        s += v; q = fmaf(v, v, q);
    }
    block_reduce2(s, q, shs, shq);
    if (threadIdx.x == 0) {
        g_part[(b * 512 + c) * 2 + 0] = s;
        g_part[(b * 512 + c) * 2 + 1] = q;
    }
}

// ---------------- FFMA2 register core (8x8 tile as 8x4 packed pairs) ----------
struct GemmCore {
    unsigned long long acc2[8][4];
    __device__ __forceinline__ void init() {
#pragma unroll
        for (int r = 0; r < 8; r++)
#pragma unroll
            for (int c = 0; c < 4; c++) acc2[r][c] = 0ULL;
    }
    __device__ __forceinline__ void step(const float (*Wsm)[128], const float (*Xsm)[128],
                                         int tx, int ty) {
#pragma unroll
        for (int kk = 0; kk < 16; kk++) {
            const unsigned long long* Xp =
                reinterpret_cast<const unsigned long long*>(&Xsm[kk][tx * 8]);
            unsigned long long x2[4];
            x2[0] = Xp[0]; x2[1] = Xp[1]; x2[2] = Xp[2]; x2[3] = Xp[3];
            const float* Wp = &Wsm[kk][ty * 8];
#pragma unroll
            for (int r = 0; r < 8; r++) {
                float w = Wp[r];
                unsigned long long w2;
                PACK2(w2, w, w);
                FFMA2(acc2[r][0], w2, x2[0]);
                FFMA2(acc2[r][1], w2, x2[1]);
                FFMA2(acc2[r][2], w2, x2[2]);
                FFMA2(acc2[r][3], w2, x2[3]);
            }
        }
    }
    __device__ __forceinline__ void row(int r, float* out8) const {
#pragma unroll
        for (int c = 0; c < 4; c++) { UNPACK2(out8[2 * c], out8[2 * c + 1], acc2[r][c]); }
    }
};

// staging helpers -------------------------------------------------------------
__device__ __forceinline__ void stageW(const float* __restrict__ src, float (*Wsm)[128]) {
#pragma unroll
    for (int e = 0; e < 2; e++) {
        int f = threadIdx.x + e * 256;       // 0..511
        int kk = f >> 5, mq = f & 31;
        uint32_t d = smem_u32(&Wsm[kk][mq * 4]);
        CP16(d, src + (size_t)kk * 128 + mq * 4);
    }
}
__device__ __forceinline__ void stageX_async(const float* __restrict__ Xb, int k0, int n0,
                                             float (*Xsm)[128]) {
#pragma unroll
    for (int e = 0; e < 2; e++) {
        int f = threadIdx.x + e * 256;
        int c4 = f & 31, kk = f >> 5;
        uint32_t d = smem_u32(&Xsm[kk][c4 * 4]);
        CP16(d, Xb + (size_t)(k0 + kk) * TLEN + n0 + c4 * 4);
    }
}

// ---------------- pipelined fused pointwise GEMM (M128 x N128) ---------------
// WS: 1 = weights from g_Ws per-batch folded slots (+g_corr bias); 0 = g_Wt+wtOff
// INMODE: 0 = raw (cp.async X), 2 = PReLU-on-load
// OUTMODE: 0 = store, 1 = dual add (by0->skip, by1->feats), 2 = PReLU+store+stats, 3 = sigmoid+store
template<int WS, int INMODE, int OUTMODE>
__global__ __launch_bounds__(256, 2)
void k_gemm(const float* __restrict__ Xin, size_t wtOff,
            const float* __restrict__ bias, float* __restrict__ Out,
            int Ktot, int Mtot, const float* __restrict__ aprelu) {
    __shared__ float Wsm[3][16][128];
    __shared__ float Xsm[3][16][128];
    __shared__ float shs[256], shq[256];
    int tid = threadIdx.x;
    int tx = tid & 15, ty = tid >> 4;
    int n0 = blockIdx.x * 128;
    int by = blockIdx.y;
    int b  = blockIdx.z;
    const float* Xb = Xin + (size_t)b * Ktot * TLEN;
    const float* wbase = WS ? g_Ws + ((size_t)(b * 2 + by)) * 65536
                            : g_Wt + wtOff + (size_t)by * Ktot * 128;
    const float* biasp = WS ? g_corr + (b * 2 + by) * 128 : bias;

    float* OutP;
    size_t obase;
    int m0;
    if (WS && OUTMODE == 1) {
        OutP = (by == 0 ? g_skip : g_feats) + (size_t)b * BFT * TLEN;
        obase = 0; m0 = 0;
    } else {
        OutP = Out; obase = (size_t)b * Mtot; m0 = by * 128;
    }

    float aval = 0.f;
    if (INMODE == 2 || OUTMODE == 2) { aval = *aprelu; }

    GemmCore core;
    core.init();
    const int NIT = Ktot / 16;

    float4 xr0, xr1;
    auto ldgX = [&](int it) {
        int f0 = tid, f1 = tid + 256;
        int kg0 = it * 16 + (f0 >> 5), kg1 = it * 16 + (f1 >> 5);
        xr0 = *reinterpret_cast<const float4*>(&Xb[(size_t)kg0 * TLEN + n0 + (f0 & 31) * 4]);
        xr1 = *reinterpret_cast<const float4*>(&Xb[(size_t)kg1 * TLEN + n0 + (f1 & 31) * 4]);
    };
    auto stsX = [&](float (*Xs)[128]) {
        float4 v0 = xr0, v1 = xr1;
        v0.x = (v0.x < 0.f) ? v0.x * aval : v0.x; v0.y = (v0.y < 0.f) ? v0.y * aval : v0.y;
        v0.z = (v0.z < 0.f) ? v0.z * aval : v0.z; v0.w = (v0.w < 0.f) ? v0.w * aval : v0.w;
        v1.x = (v1.x < 0.f) ? v1.x * aval : v1.x; v1.y = (v1.y < 0.f) ? v1.y * aval : v1.y;
        v1.z = (v1.z < 0.f) ? v1.z * aval : v1.z; v1.w = (v1.w < 0.f) ? v1.w * aval : v1.w;
        int f0 = tid, f1 = tid + 256;
        *reinterpret_cast<float4*>(&Xs[f0 >> 5][(f0 & 31) * 4]) = v0;
        *reinterpret_cast<float4*>(&Xs[f1 >> 5][(f1 & 31) * 4]) = v1;
    };

    if (INMODE == 0) {
        stageW(wbase, Wsm[0]); stageX_async(Xb, 0, n0, Xsm[0]); CPCOMMIT();
        stageW(wbase + (size_t)16 * 128, Wsm[1]); stageX_async(Xb, 16, n0, Xsm[1]); CPCOMMIT();
    } else {
        ldgX(0); stageW(wbase, Wsm[0]); CPCOMMIT(); stsX(Xsm[0]);
        ldgX(1); stageW(wbase + (size_t)16 * 128, Wsm[1]); CPCOMMIT(); stsX(Xsm[1]);
    }

    for (int i = 0; i < NIT; i++) {
        CPWAIT1();
        __syncthreads();
        bool more = (i + 2) < NIT;
        int nb = (i + 2) % 3;
        if (more) {
            stageW(wbase + (size_t)(i + 2) * 16 * 128, Wsm[nb]);
            if (INMODE == 0) stageX_async(Xb, (i + 2) * 16, n0, Xsm[nb]);
            else             ldgX(i + 2);
        }
        CPCOMMIT();
        core.step(Wsm[i % 3], Xsm[i % 3], tx, ty);
        if (more && INMODE != 0) stsX(Xsm[nb]);
    }

    // epilogue
    float ls = 0.f, lq = 0.f;
#pragma unroll
    for (int r = 0; r < 8; r++) {
        int o = m0 + ty * 8 + r;
        float bv = biasp[o];
        float a8[8];
        core.row(r, a8);
        float* po = OutP + (obase + o) * TLEN + n0 + tx * 8;
#pragma unroll
        for (int h = 0; h < 2; h++) {
            float4 v;
            v.x = a8[h * 4 + 0] + bv;
            v.y = a8[h * 4 + 1] + bv;
            v.z = a8[h * 4 + 2] + bv;
            v.w = a8[h * 4 + 3] + bv;
            if (OUTMODE == 1) {
                float4 old = *reinterpret_cast<const float4*>(&po[h * 4]);
                v.x += old.x; v.y += old.y; v.z += old.z; v.w += old.w;
            } else if (OUTMODE == 2) {
                v.x = (v.x < 0.f) ? v.x * aval : v.x;
                v.y = (v.y < 0.f) ? v.y * aval : v.y;
                v.z = (v.z < 0.f) ? v.z * aval : v.z;
                v.w = (v.w < 0.f) ? v.w * aval : v.w;
                ls += v.x + v.y + v.z + v.w;
                lq = fmaf(v.x, v.x, lq); lq = fmaf(v.y, v.y, lq);
                lq = fmaf(v.z, v.z, lq); lq = fmaf(v.w, v.w, lq);
            } else if (OUTMODE == 3) {
                v.x = 1.f / (1.f + __expf(-v.x));
                v.y = 1.f / (1.f + __expf(-v.y));
                v.z = 1.f / (1.f + __expf(-v.z));
                v.w = 1.f / (1.f + __expf(-v.w));
            }
            *reinterpret_cast<float4*>(&po[h * 4]) = v;
        }
    }
    if (OUTMODE == 2) {
        block_reduce2(ls, lq, shs, shq);
        if (tid == 0) {
            int pid = by * gridDim.x + blockIdx.x;   // < 100
            g_part[(b * 512 + pid) * 2 + 0] = ls;
            g_part[(b * 512 + pid) * 2 + 1] = lq;
        }
    }
    CPWAIT0();
}

// ---------------- host launch ----------------
extern "C" void kernel_launch(void* const* d_in, const int* in_sizes, int n_in,
                              void* d_out, int out_size) {
    const float* x    = (const float*)d_in[0];
    const float* in_g = (const float*)d_in[1];
    const float* in_b = (const float*)d_in[2];
    const float* Wc   = (const float*)d_in[3];
    const float* bc   = (const float*)d_in[4];
    const float* W1   = (const float*)d_in[5];
    const float* b1   = (const float*)d_in[6];
    const float* a1   = (const float*)d_in[7];
    const float* g1   = (const float*)d_in[8];
    const float* be1  = (const float*)d_in[9];
    const float* Wd   = (const float*)d_in[10];
    const float* bd   = (const float*)d_in[11];
    const float* a2   = (const float*)d_in[12];
    const float* g2   = (const float*)d_in[13];
    const float* be2  = (const float*)d_in[14];
    const float* Wres = (const float*)d_in[15];
    const float* bres = (const float*)d_in[16];
    const float* Wsk  = (const float*)d_in[17];
    const float* bsk  = (const float*)d_in[18];
    const float* aout = (const float*)d_in[19];
    const float* Wo   = (const float*)d_in[20];
    const float* bo   = (const float*)d_in[21];
    float* out = (float*)d_out;

    float *p_feats, *p_skip, *p_h, *p_h2;
    cudaGetSymbolAddress((void**)&p_feats, g_feats);
    cudaGetSymbolAddress((void**)&p_skip,  g_skip);
    cudaGetSymbolAddress((void**)&p_h,     g_h);
    cudaGetSymbolAddress((void**)&p_h2,    g_h2);

    const float denomN = (float)((size_t)NCH * TLEN);
    const float denomH = (float)((size_t)HID * TLEN);

    // Launch order: index 5 (ncu -s 5 -c 1) = the feats GEMM (shared GEMM core).
    k_wt<<<dim3(16, 4),   256>>>(Wc,   512, (size_t)OFF_WC);      // 0
    k_wt<<<dim3(4, 384),  256>>>(W1,   128, (size_t)OFF_W1);      // 1
    {
        int n4 = BATCH * BFT * TLEN / 4;
        k_zero<<<(n4 + 255) / 256, 256>>>(p_skip, n4);            // 2
    }
    k_rowstats<<<dim3(NCH, BATCH), 256>>>(x);                     // 3
    k_scalew<<<dim3(1, BATCH), 256>>>((size_t)OFF_WC, (size_t)OFF_WC,
                                      bc, bc, in_g, in_b, 512, denomN);   // 4
    // feats = Wc' @ x + corr   (folded gLN, pure cp.async)
    k_gemm<1, 0, 0><<<dim3(25, 1, BATCH), 256>>>(
        x, 0, nullptr, p_feats, NCH, BFT, nullptr);               // 5 <- profiled

    k_wt<<<dim3(16, 96),  256>>>(Wsk,  512, (size_t)OFF_WSK);
    k_wt<<<dim3(16, 96),  256>>>(Wres, 512, (size_t)OFF_WRES);
    k_wt<<<dim3(4, 32),   256>>>(Wo,   128, (size_t)OFF_WO);

    for (int i = 0; i < LAY; i++) {
        int dil = 1 << (i & 7);
        // h = prelu(W1 @ feats + b1) + stats partials (100)
        k_gemm<0, 0, 2><<<dim3(25, 4, BATCH), 256>>>(
            p_feats, (size_t)(OFF_W1 + (size_t)i * 65536), b1 + (size_t)i * HID, p_h,
            BFT, HID, a1 + i);
        // h2 = prelu(dwconv(gln1(h))) + stats partials (512)
        k_dw<<<dim3(HID, BATCH), 256>>>(Wd, bd, g1, be1, a2, i, dil, denomH);
        // fold gln2 into Wsk/Wres
        int ny = (i < LAY - 1) ? 2 : 1;
        k_scalew<<<dim3(ny, BATCH), 256>>>(
            (size_t)(OFF_WSK + (size_t)i * 65536), (size_t)(OFF_WRES + (size_t)i * 65536),
            bsk + (size_t)i * BFT, bres + (size_t)i * BFT,
            g2 + (size_t)i * HID, be2 + (size_t)i * HID, 512, denomH);
        // skip (+ residual), folded weights, raw h2, add-mode
        k_gemm<1, 0, 1><<<dim3(25, ny, BATCH), 256>>>(
            p_h2, 0, nullptr, nullptr, HID, BFT, nullptr);
    }

    // out = sigmoid(Wo @ prelu(skip) + bo)
    k_gemm<0, 2, 3><<<dim3(25, 8, BATCH), 256>>>(
        p_skip, (size_t)OFF_WO, bo, out, BFT, NSRC * NCH, aout);
}

// round 12
// speedup vs baseline: 1.0623x; 1.0623x over previous
#include <cuda_runtime.h>
#include <math.h>
#include <stdint.h>

#define BATCH 8
#define NCH   512     // encoder feats
#define BFT   128     // bottleneck
#define HID   512     // hidden
#define TLEN  3200
#define LAY   24
#define NSRC  2
#define EPSV  1e-8f

// dynamic smem: W 3 stages x 16 x 256 (dup pairs, built during staging) + X 3 x 16 x 128
#define WST_FLOATS (16 * 256)
#define XST_FLOATS (16 * 128)
#define SMEMSZ ((3 * WST_FLOATS + 3 * XST_FLOATS) * 4)   // 73728 bytes

// ---------------- scratch (device globals; no allocs allowed) ----------------
__device__ float g_feats[BATCH * BFT * TLEN];   // [b][c][t]
__device__ float g_h    [BATCH * HID * TLEN];
__device__ float g_h2   [BATCH * HID * TLEN];
__device__ float g_skip [BATCH * BFT * TLEN];
__device__ float g_part [BATCH * 512 * 2];      // fixed-slot partials (sum,sumsq)

// transposed weights (R7 layout, single-width, batch-shared): [mt][k][ml]
#define OFF_WC   0
#define OFF_W1   65536
#define OFF_WSK  (OFF_W1  + 24 * 65536)
#define OFF_WRES (OFF_WSK + 24 * 65536)
#define OFF_WO   (OFF_WRES + 24 * 65536)
__device__ float g_Wt[OFF_WO + 8 * 16384];

// ---------------- packed f32x2 helpers ----------------
#define FFMA2(acc, a, b) \
    asm("fma.rn.f32x2 %0, %1, %2, %0;" : "+l"(acc) : "l"(a), "l"(b))
#define UNPACK2(lo, hi, in) \
    { unsigned int _ulo, _uhi; \
      asm("mov.b64 {%0, %1}, %2;" : "=r"(_ulo), "=r"(_uhi) : "l"(in)); \
      lo = __uint_as_float(_ulo); hi = __uint_as_float(_uhi); }

// ---------------- cp.async ----------------
__device__ __forceinline__ uint32_t smem_u32(const void* p) {
    uint32_t a;
    asm("{ .reg .u64 t; cvta.to.shared.u64 t, %1; cvt.u32.u64 %0, t; }" : "=r"(a) : "l"(p));
    return a;
}
#define CP16(dst, src)  asm volatile("cp.async.cg.shared.global [%0], [%1], 16;" :: "r"(dst), "l"(src))
#define CPCOMMIT()      asm volatile("cp.async.commit_group;")
#define CPWAIT1()       asm volatile("cp.async.wait_group 1;")
#define CPWAIT0()       asm volatile("cp.async.wait_group 0;")

// ---------------- helpers ----------------
__device__ __forceinline__ void block_reduce2(float& s, float& q, float* shs, float* shq) {
    int tid = threadIdx.x;
    shs[tid] = s; shq[tid] = q;
    __syncthreads();
    for (int st = 128; st > 0; st >>= 1) {
        if (tid < st) { shs[tid] += shs[tid + st]; shq[tid] += shq[tid + st]; }
        __syncthreads();
    }
    s = shs[0]; q = shq[0];
}

__device__ __forceinline__ void stats_from_part(int b, int pcount, float denom,
                                                float& mean, float& rstd,
                                                float* shs, float* shq) {
    float s = 0.f, q = 0.f;
    for (int j = threadIdx.x; j < pcount; j += 256) {
        s += g_part[(b * 512 + j) * 2 + 0];
        q += g_part[(b * 512 + j) * 2 + 1];
    }
    block_reduce2(s, q, shs, shq);
    mean = s / denom;
    float var = fmaxf(q / denom - mean * mean, 0.f);
    rstd = rsqrtf(var + EPSV);
}

__global__ void k_zero(float* __restrict__ p, int n4) {
    int i = blockIdx.x * blockDim.x + threadIdx.x;
    if (i < n4) reinterpret_cast<float4*>(p)[i] = make_float4(0.f, 0.f, 0.f, 0.f);
}

// transpose weights: src [Mtot][Ktot] -> g_Wt[dstOff + (mt*Ktot + k)*128 + ml]
__global__ void k_wt(const float* __restrict__ src, int Ktot, size_t dstOff) {
    __shared__ float t[32][33];
    int k0 = blockIdx.x * 32, m0 = blockIdx.y * 32;
    int lx = threadIdx.x & 31, ly = threadIdx.x >> 5;
#pragma unroll
    for (int i = 0; i < 4; i++)
        t[ly + i * 8][lx] = src[(size_t)(m0 + ly + i * 8) * Ktot + k0 + lx];
    __syncthreads();
#pragma unroll
    for (int i = 0; i < 4; i++) {
        int k = k0 + ly + i * 8;
        int m = m0 + lx;
        g_Wt[dstOff + ((size_t)(m >> 7) * Ktot + k) * 128 + (m & 127)] = t[lx][ly + i * 8];
    }
}

// per-row stats for input x [b][c][t]
__global__ void k_rowstats(const float* __restrict__ X) {
    int c = blockIdx.x, b = blockIdx.y;
    const float* p = X + ((size_t)b * NCH + c) * TLEN;
    float s = 0.f, q = 0.f;
    for (int t = threadIdx.x; t < TLEN; t += 256) {
        float v = p[t];
        s += v; q += v * v;
    }
    __shared__ float shs[256], shq[256];
    block_reduce2(s, q, shs, shq);
    if (threadIdx.x == 0) {
        g_part[(b * 512 + c) * 2 + 0] = s;
        g_part[(b * 512 + c) * 2 + 1] = q;
    }
}

// fused gLN1 + depthwise dilated conv + PReLU + stats (reduces 100 h-partials itself)
__global__ void k_dw(const float* __restrict__ Wd, const float* __restrict__ bd,
                     const float* __restrict__ g1, const float* __restrict__ be1,
                     const float* __restrict__ a2, int layer, int dil, float denom) {
    __shared__ float shs[256], shq[256];
    int c = blockIdx.x, b = blockIdx.y;
    float mean, rstd;
    stats_from_part(b, 100, denom, mean, rstd, shs, shq);
    __syncthreads();
    int lc = layer * HID + c;
    float ga = g1[lc] * rstd;
    float dd = be1[lc] - ga * mean;
    float w0 = Wd[lc * 3 + 0], w1 = Wd[lc * 3 + 1], w2 = Wd[lc * 3 + 2];
    float bv = bd[lc];
    float al = a2[layer];
    const float* ph = g_h  + ((size_t)b * HID + c) * TLEN;
    float*       po = g_h2 + ((size_t)b * HID + c) * TLEN;
    float s = 0.f, q = 0.f;
    for (int t = threadIdx.x; t < TLEN; t += 256) {
        float ctr = ga * ph[t] + dd;
        float lf  = (t >= dil)        ? ga * ph[t - dil] + dd : 0.f;
        float rt  = (t + dil < TLEN)  ? ga * ph[t + dil] + dd : 0.f;
        float v = fmaf(w0, lf, fmaf(w1, ctr, fmaf(w2, rt, bv)));
        v = (v < 0.f) ? al * v : v;
        po[t] = v;
        s += v; q = fmaf(v, v, q);
    }
    block_reduce2(s, q, shs, shq);
    if (threadIdx.x == 0) {
        g_part[(b * 512 + c) * 2 + 0] = s;
        g_part[(b * 512 + c) * 2 + 1] = q;
    }
}

// ---------------- FFMA2 core: 8x8 tile, W read as smem-dup 64-bit pairs -------
// tx = tid&15 (cols tx*8..+7), ty = tid>>4 (rows ty*8..+7)
struct GemmCore {
    unsigned long long acc2[8][4];
    __device__ __forceinline__ void init() {
#pragma unroll
        for (int r = 0; r < 8; r++)
#pragma unroll
            for (int c = 0; c < 4; c++) acc2[r][c] = 0ULL;
    }
    // Wst: 16 x 256 floats (dup pairs); Xst: 16 x 128 floats
    __device__ __forceinline__ void step(const float* __restrict__ Wst,
                                         const float* __restrict__ Xst,
                                         int tx, int ty) {
#pragma unroll
        for (int kk = 0; kk < 16; kk++) {
            const unsigned long long* Xp =
                reinterpret_cast<const unsigned long long*>(Xst + kk * 128 + tx * 8);
            unsigned long long x2[4];
            x2[0] = Xp[0]; x2[1] = Xp[1]; x2[2] = Xp[2]; x2[3] = Xp[3];
            const unsigned long long* Wp =
                reinterpret_cast<const unsigned long long*>(Wst + kk * 256 + ty * 16);
#pragma unroll
            for (int r = 0; r < 8; r++) {
                unsigned long long w2 = Wp[r];
                FFMA2(acc2[r][0], w2, x2[0]);
                FFMA2(acc2[r][1], w2, x2[1]);
                FFMA2(acc2[r][2], w2, x2[2]);
                FFMA2(acc2[r][3], w2, x2[3]);
            }
        }
    }
    __device__ __forceinline__ void row(int r, float* out8) const {
#pragma unroll
        for (int c = 0; c < 4; c++) { UNPACK2(out8[2 * c], out8[2 * c + 1], acc2[r][c]); }
    }
};

// X tile raw (cp.async), as R7
__device__ __forceinline__ void stageX_async(const float* __restrict__ Xb, int k0, int n0,
                                             float* Xst) {
#pragma unroll
    for (int e = 0; e < 2; e++) {
        int f = threadIdx.x + e * 256;
        int c4 = f & 31, kk = f >> 5;
        uint32_t d = smem_u32(Xst + kk * 128 + c4 * 4);
        CP16(d, Xb + (size_t)(k0 + kk) * TLEN + n0 + c4 * 4);
    }
}

// ---------------- pipelined fused pointwise GEMM (M128 x N128) ---------------
// W staged via register prefetch + duplicated STS (smem-only duplication).
// INMODE: 0 = raw (cp.async X), 1 = gLN-on-load, 2 = PReLU-on-load
// OUTMODE: 0 = store, 1 = add, 2 = PReLU+store+stats, 3 = sigmoid+store
template<int INMODE, int OUTMODE>
__global__ __launch_bounds__(256, 2)
void k_gemm(const float* __restrict__ Xin, size_t wtOff,
            const float* __restrict__ bias, float* __restrict__ Out,
            int Ktot, int Mtot,
            const float* __restrict__ gvec, const float* __restrict__ bvec,
            const float* __restrict__ aprelu, int pcount, float denom) {
    extern __shared__ float S[];
    float* Wsm = S;                        // 3 x WST_FLOATS
    float* Xsm = S + 3 * WST_FLOATS;       // 3 x XST_FLOATS
    __shared__ float shs[256], shq[256];
    int tid = threadIdx.x;
    int tx = tid & 15, ty = tid >> 4;
    int n0 = blockIdx.x * 128;
    int by = blockIdx.y;
    int b  = blockIdx.z;
    const float* Xb = Xin + (size_t)b * Ktot * TLEN;
    const float* wbase = g_Wt + wtOff + (size_t)by * Ktot * 128;

    float mean = 0.f, rstd = 0.f, aval = 0.f;
    if (INMODE == 1) {
        stats_from_part(b, pcount, denom, mean, rstd, shs, shq);
        __syncthreads();
    }
    if (INMODE == 2 || OUTMODE == 2) { aval = *aprelu; }

    GemmCore core;
    core.init();
    const int NIT = Ktot / 16;

    // W register prefetch (2 x float4 per thread per K-chunk)
    float4 wr0, wr1;
    const int wkk0 = tid >> 5, wmq0 = tid & 31;            // element 0
    const int wkk1 = (tid + 256) >> 5, wmq1 = tid & 31;    // element 1 (same mq bits)
    auto ldgW = [&](int it) {
        const float* src = wbase + (size_t)it * 16 * 128;
        wr0 = *reinterpret_cast<const float4*>(src + (size_t)wkk0 * 128 + wmq0 * 4);
        wr1 = *reinterpret_cast<const float4*>(src + (size_t)wkk1 * 128 + wmq1 * 4);
    };
    auto stsW = [&](float* Wst) {
        float* d0 = Wst + wkk0 * 256 + wmq0 * 8;
        float* d1 = Wst + wkk1 * 256 + wmq1 * 8;
        *reinterpret_cast<float4*>(d0)     = make_float4(wr0.x, wr0.x, wr0.y, wr0.y);
        *reinterpret_cast<float4*>(d0 + 4) = make_float4(wr0.z, wr0.z, wr0.w, wr0.w);
        *reinterpret_cast<float4*>(d1)     = make_float4(wr1.x, wr1.x, wr1.y, wr1.y);
        *reinterpret_cast<float4*>(d1 + 4) = make_float4(wr1.z, wr1.z, wr1.w, wr1.w);
    };

    // X register path (INMODE 1/2)
    float4 xr0, xr1;
    float ac0 = 0.f, dc0 = 0.f, ac1 = 0.f, dc1 = 0.f;
    auto ldgX = [&](int it) {
        int f0 = tid, f1 = tid + 256;
        int kg0 = it * 16 + (f0 >> 5), kg1 = it * 16 + (f1 >> 5);
        xr0 = *reinterpret_cast<const float4*>(&Xb[(size_t)kg0 * TLEN + n0 + (f0 & 31) * 4]);
        xr1 = *reinterpret_cast<const float4*>(&Xb[(size_t)kg1 * TLEN + n0 + (f1 & 31) * 4]);
        if (INMODE == 1) {
            ac0 = gvec[kg0] * rstd; dc0 = bvec[kg0] - ac0 * mean;
            ac1 = gvec[kg1] * rstd; dc1 = bvec[kg1] - ac1 * mean;
        }
    };
    auto stsX = [&](float* Xst) {
        float4 v0 = xr0, v1 = xr1;
        if (INMODE == 1) {
            v0.x = fmaf(ac0, v0.x, dc0); v0.y = fmaf(ac0, v0.y, dc0);
            v0.z = fmaf(ac0, v0.z, dc0); v0.w = fmaf(ac0, v0.w, dc0);
            v1.x = fmaf(ac1, v1.x, dc1); v1.y = fmaf(ac1, v1.y, dc1);
            v1.z = fmaf(ac1, v1.z, dc1); v1.w = fmaf(ac1, v1.w, dc1);
        } else if (INMODE == 2) {
            v0.x = (v0.x < 0.f) ? v0.x * aval : v0.x; v0.y = (v0.y < 0.f) ? v0.y * aval : v0.y;
            v0.z = (v0.z < 0.f) ? v0.z * aval : v0.z; v0.w = (v0.w < 0.f) ? v0.w * aval : v0.w;
            v1.x = (v1.x < 0.f) ? v1.x * aval : v1.x; v1.y = (v1.y < 0.f) ? v1.y * aval : v1.y;
            v1.z = (v1.z < 0.f) ? v1.z * aval : v1.z; v1.w = (v1.w < 0.f) ? v1.w * aval : v1.w;
        }
        int f0 = tid, f1 = tid + 256;
        *reinterpret_cast<float4*>(Xst + (f0 >> 5) * 128 + (f0 & 31) * 4) = v0;
        *reinterpret_cast<float4*>(Xst + (f1 >> 5) * 128 + (f1 & 31) * 4) = v1;
    };

    // prologue: stages 0 and 1 (W direct; X cp.async or reg path)
    ldgW(0); stsW(Wsm);
    ldgW(1); stsW(Wsm + WST_FLOATS);
    if (INMODE == 0) {
        stageX_async(Xb, 0, n0, Xsm); CPCOMMIT();
        stageX_async(Xb, 16, n0, Xsm + XST_FLOATS); CPCOMMIT();
    } else {
        ldgX(0); stsX(Xsm);
        ldgX(1); stsX(Xsm + XST_FLOATS);
    }

    for (int i = 0; i < NIT; i++) {
        if (INMODE == 0) CPWAIT1();
        __syncthreads();
        bool more = (i + 2) < NIT;
        int nb = (i + 2) % 3;
        if (more) {
            ldgW(i + 2);
            if (INMODE == 0) { stageX_async(Xb, (i + 2) * 16, n0, Xsm + nb * XST_FLOATS); CPCOMMIT(); }
            else             ldgX(i + 2);
        } else if (INMODE == 0) CPCOMMIT();
        core.step(Wsm + (i % 3) * WST_FLOATS, Xsm + (i % 3) * XST_FLOATS, tx, ty);
        if (more) {
            stsW(Wsm + nb * WST_FLOATS);
            if (INMODE != 0) stsX(Xsm + nb * XST_FLOATS);
        }
    }

    // epilogue
    int m0 = by * 128;
    float ls = 0.f, lq = 0.f;
#pragma unroll
    for (int r = 0; r < 8; r++) {
        int o = m0 + ty * 8 + r;
        float bv = bias[o];
        float a8[8];
        core.row(r, a8);
        float* po = Out + ((size_t)b * Mtot + o) * TLEN + n0 + tx * 8;
#pragma unroll
        for (int h = 0; h < 2; h++) {
            float4 v;
            v.x = a8[h * 4 + 0] + bv;
            v.y = a8[h * 4 + 1] + bv;
            v.z = a8[h * 4 + 2] + bv;
            v.w = a8[h * 4 + 3] + bv;
            if (OUTMODE == 1) {
                float4 old = *reinterpret_cast<const float4*>(&po[h * 4]);
                v.x += old.x; v.y += old.y; v.z += old.z; v.w += old.w;
            } else if (OUTMODE == 2) {
                v.x = (v.x < 0.f) ? v.x * aval : v.x;
                v.y = (v.y < 0.f) ? v.y * aval : v.y;
                v.z = (v.z < 0.f) ? v.z * aval : v.z;
                v.w = (v.w < 0.f) ? v.w * aval : v.w;
                ls += v.x + v.y + v.z + v.w;
                lq = fmaf(v.x, v.x, lq); lq = fmaf(v.y, v.y, lq);
                lq = fmaf(v.z, v.z, lq); lq = fmaf(v.w, v.w, lq);
            } else if (OUTMODE == 3) {
                v.x = 1.f / (1.f + __expf(-v.x));
                v.y = 1.f / (1.f + __expf(-v.y));
                v.z = 1.f / (1.f + __expf(-v.z));
                v.w = 1.f / (1.f + __expf(-v.w));
            }
            *reinterpret_cast<float4*>(&po[h * 4]) = v;
        }
    }
    if (OUTMODE == 2) {
        block_reduce2(ls, lq, shs, shq);
        if (tid == 0) {
            int pid = by * gridDim.x + blockIdx.x;   // < 100
            g_part[(b * 512 + pid) * 2 + 0] = ls;
            g_part[(b * 512 + pid) * 2 + 1] = lq;
        }
    }
    if (INMODE == 0) CPWAIT0();
}

// ---------------- dual-output pipelined GEMM: skip + residual -----------------
__global__ __launch_bounds__(256, 2)
void k_gemm_dual(size_t offSk, size_t offRes,
                 const float* __restrict__ biasSk, const float* __restrict__ biasRes,
                 const float* __restrict__ gvec, const float* __restrict__ bvec,
                 float denom) {
    extern __shared__ float S[];
    float* Wsm = S;
    float* Xsm = S + 3 * WST_FLOATS;
    __shared__ float shs[256], shq[256];
    const int Ktot = HID;
    int tid = threadIdx.x;
    int tx = tid & 15, ty = tid >> 4;
    int n0 = blockIdx.x * 128;
    int by = blockIdx.y;
    int b  = blockIdx.z;
    const float* Xb = g_h2 + (size_t)b * Ktot * TLEN;
    const float* wbase = g_Wt + (by == 0 ? offSk : offRes);
    const float* bias  = (by == 0) ? biasSk : biasRes;
    float* Out = (by == 0) ? (g_skip + (size_t)b * BFT * TLEN)
                           : (g_feats + (size_t)b * BFT * TLEN);

    float mean, rstd;
    stats_from_part(b, 512, denom, mean, rstd, shs, shq);
    __syncthreads();

    GemmCore core;
    core.init();
    const int NIT = Ktot / 16;

    float4 wr0, wr1;
    const int wkk0 = tid >> 5, wmq0 = tid & 31;
    const int wkk1 = (tid + 256) >> 5, wmq1 = tid & 31;
    auto ldgW = [&](int it) {
        const float* src = wbase + (size_t)it * 16 * 128;
        wr0 = *reinterpret_cast<const float4*>(src + (size_t)wkk0 * 128 + wmq0 * 4);
        wr1 = *reinterpret_cast<const float4*>(src + (size_t)wkk1 * 128 + wmq1 * 4);
    };
    auto stsW = [&](float* Wst) {
        float* d0 = Wst + wkk0 * 256 + wmq0 * 8;
        float* d1 = Wst + wkk1 * 256 + wmq1 * 8;
        *reinterpret_cast<float4*>(d0)     = make_float4(wr0.x, wr0.x, wr0.y, wr0.y);
        *reinterpret_cast<float4*>(d0 + 4) = make_float4(wr0.z, wr0.z, wr0.w, wr0.w);
        *reinterpret_cast<float4*>(d1)     = make_float4(wr1.x, wr1.x, wr1.y, wr1.y);
        *reinterpret_cast<float4*>(d1 + 4) = make_float4(wr1.z, wr1.z, wr1.w, wr1.w);
    };

    float4 xr0, xr1;
    float ac0, dc0, ac1, dc1;
    auto ldgX = [&](int it) {
        int f0 = tid, f1 = tid + 256;
        int kg0 = it * 16 + (f0 >> 5), kg1 = it * 16 + (f1 >> 5);
        xr0 = *reinterpret_cast<const float4*>(&Xb[(size_t)kg0 * TLEN + n0 + (f0 & 31) * 4]);
        xr1 = *reinterpret_cast<const float4*>(&Xb[(size_t)kg1 * TLEN + n0 + (f1 & 31) * 4]);
        ac0 = gvec[kg0] * rstd; dc0 = bvec[kg0] - ac0 * mean;
        ac1 = gvec[kg1] * rstd; dc1 = bvec[kg1] - ac1 * mean;
    };
    auto stsX = [&](float* Xst) {
        float4 v0 = xr0, v1 = xr1;
        v0.x = fmaf(ac0, v0.x, dc0); v0.y = fmaf(ac0, v0.y, dc0);
        v0.z = fmaf(ac0, v0.z, dc0); v0.w = fmaf(ac0, v0.w, dc0);
        v1.x = fmaf(ac1, v1.x, dc1); v1.y = fmaf(ac1, v1.y, dc1);
        v1.z = fmaf(ac1, v1.z, dc1); v1.w = fmaf(ac1, v1.w, dc1);
        int f0 = tid, f1 = tid + 256;
        *reinterpret_cast<float4*>(Xst + (f0 >> 5) * 128 + (f0 & 31) * 4) = v0;
        *reinterpret_cast<float4*>(Xst + (f1 >> 5) * 128 + (f1 & 31) * 4) = v1;
    };

    ldgW(0); stsW(Wsm);
    ldgW(1); stsW(Wsm + WST_FLOATS);
    ldgX(0); stsX(Xsm);
    ldgX(1); stsX(Xsm + XST_FLOATS);

    for (int i = 0; i < NIT; i++) {
        __syncthreads();
        bool more = (i + 2) < NIT;
        int nb = (i + 2) % 3;
        if (more) { ldgW(i + 2); ldgX(i + 2); }
        core.step(Wsm + (i % 3) * WST_FLOATS, Xsm + (i % 3) * XST_FLOATS, tx, ty);
        if (more) { stsW(Wsm + nb * WST_FLOATS); stsX(Xsm + nb * XST_FLOATS); }
    }

#pragma unroll
    for (int r = 0; r < 8; r++) {
        int o = ty * 8 + r;
        float bv = bias[o];
        float a8[8];
        core.row(r, a8);
        float* po = Out + (size_t)o * TLEN + n0 + tx * 8;
#pragma unroll
        for (int h = 0; h < 2; h++) {
            float4 old = *reinterpret_cast<const float4*>(&po[h * 4]);
            float4 v;
            v.x = a8[h * 4 + 0] + bv + old.x;
            v.y = a8[h * 4 + 1] + bv + old.y;
            v.z = a8[h * 4 + 2] + bv + old.z;
            v.w = a8[h * 4 + 3] + bv + old.w;
            *reinterpret_cast<float4*>(&po[h * 4]) = v;
        }
    }
}

// ---------------- host launch ----------------
extern "C" void kernel_launch(void* const* d_in, const int* in_sizes, int n_in,
                              void* d_out, int out_size) {
    const float* x    = (const float*)d_in[0];
    const float* in_g = (const float*)d_in[1];
    const float* in_b = (const float*)d_in[2];
    const float* Wc   = (const float*)d_in[3];
    const float* bc   = (const float*)d_in[4];
    const float* W1   = (const float*)d_in[5];
    const float* b1   = (const float*)d_in[6];
    const float* a1   = (const float*)d_in[7];
    const float* g1   = (const float*)d_in[8];
    const float* be1  = (const float*)d_in[9];
    const float* Wd   = (const float*)d_in[10];
    const float* bd   = (const float*)d_in[11];
    const float* a2   = (const float*)d_in[12];
    const float* g2   = (const float*)d_in[13];
    const float* be2  = (const float*)d_in[14];
    const float* Wres = (const float*)d_in[15];
    const float* bres = (const float*)d_in[16];
    const float* Wsk  = (const float*)d_in[17];
    const float* bsk  = (const float*)d_in[18];
    const float* aout = (const float*)d_in[19];
    const float* Wo   = (const float*)d_in[20];
    const float* bo   = (const float*)d_in[21];
    float* out = (float*)d_out;

    cudaFuncSetAttribute(k_gemm<1, 0>, cudaFuncAttributeMaxDynamicSharedMemorySize, SMEMSZ);
    cudaFuncSetAttribute(k_gemm<0, 2>, cudaFuncAttributeMaxDynamicSharedMemorySize, SMEMSZ);
    cudaFuncSetAttribute(k_gemm<2, 3>, cudaFuncAttributeMaxDynamicSharedMemorySize, SMEMSZ);
    cudaFuncSetAttribute(k_gemm_dual,  cudaFuncAttributeMaxDynamicSharedMemorySize, SMEMSZ);

    float *p_feats, *p_skip, *p_h;
    cudaGetSymbolAddress((void**)&p_feats, g_feats);
    cudaGetSymbolAddress((void**)&p_skip,  g_skip);
    cudaGetSymbolAddress((void**)&p_h,     g_h);

    const float denomN = (float)((size_t)NCH * TLEN);
    const float denomH = (float)((size_t)HID * TLEN);

    // weight transposes into tile layout [mt][k][ml]
    k_wt<<<dim3(16, 4),   256>>>(Wc,   512, (size_t)OFF_WC);
    k_wt<<<dim3(4, 384),  256>>>(W1,   128, (size_t)OFF_W1);
    k_wt<<<dim3(16, 96),  256>>>(Wsk,  512, (size_t)OFF_WSK);
    k_wt<<<dim3(16, 96),  256>>>(Wres, 512, (size_t)OFF_WRES);
    k_wt<<<dim3(4, 32),   256>>>(Wo,   128, (size_t)OFF_WO);

    // zero skip accumulator; input gLN stats
    {
        int n4 = BATCH * BFT * TLEN / 4;
        k_zero<<<(n4 + 255) / 256, 256>>>(p_skip, n4);
    }
    k_rowstats<<<dim3(NCH, BATCH), 256>>>(x);

    // feats = Wc @ gln(x) + bc  (K=512; stats reduced in-kernel from 512 partials)
    k_gemm<1, 0><<<dim3(25, 1, BATCH), 256, SMEMSZ>>>(
        x, (size_t)OFF_WC, bc, p_feats, NCH, BFT, in_g, in_b, nullptr, 512, denomN);

    for (int i = 0; i < LAY; i++) {
        int dil = 1 << (i & 7);
        // h = prelu(W1 @ feats + b1) + stats partials (100)
        k_gemm<0, 2><<<dim3(25, 4, BATCH), 256, SMEMSZ>>>(
            p_feats, (size_t)(OFF_W1 + (size_t)i * 65536), b1 + (size_t)i * HID, p_h,
            BFT, HID, nullptr, nullptr, a1 + i, 0, 0.f);
        // h2 = prelu(dwconv(gln1(h))) + stats partials (512)
        k_dw<<<dim3(HID, BATCH), 256>>>(Wd, bd, g1, be1, a2, i, dil, denomH);
        // skip (+ residual when not last), gln2-on-load, stats from 512 partials
        int ny = (i < LAY - 1) ? 2 : 1;
        k_gemm_dual<<<dim3(25, ny, BATCH), 256, SMEMSZ>>>(
            (size_t)(OFF_WSK + (size_t)i * 65536), (size_t)(OFF_WRES + (size_t)i * 65536),
            bsk + (size_t)i * BFT, bres + (size_t)i * BFT,
            g2 + (size_t)i * HID, be2 + (size_t)i * HID, denomH);
    }

    // out = sigmoid(Wo @ prelu(skip) + bo)
    k_gemm<2, 3><<<dim3(25, 8, BATCH), 256, SMEMSZ>>>(
        p_skip, (size_t)OFF_WO, bo, out, BFT, NSRC * NCH,
        nullptr, nullptr, aout, 0, 0.f);
}

// round 13
// speedup vs baseline: 1.2788x; 1.2038x over previous
#include <cuda_runtime.h>
#include <math.h>
#include <stdint.h>

#define BATCH 8
#define NCH   512     // encoder feats
#define BFT   128     // bottleneck
#define HID   512     // hidden
#define TLEN  3200
#define LAY   24
#define NSRC  2
#define EPSV  1e-8f

// ---------------- scratch (device globals; no allocs allowed) ----------------
__device__ float g_feats[BATCH * BFT * TLEN];   // 13.1 MB  [b][c][t]
__device__ float g_h    [BATCH * HID * TLEN];   // 52.4 MB
__device__ float g_h2   [BATCH * HID * TLEN];   // 52.4 MB
__device__ float g_skip [BATCH * BFT * TLEN];   // 13.1 MB
__device__ float g_part [BATCH * 512 * 2];      // fixed-slot partials (sum,sumsq)

// transposed weights: per 128-row m-tile, layout [mt][k][ml], ml in 0..127
#define OFF_WC   0
#define OFF_W1   65536                         // 24 layers x 4 mtiles x 128k x 128
#define OFF_WSK  (OFF_W1  + 24 * 65536)
#define OFF_WRES (OFF_WSK + 24 * 65536)
#define OFF_WO   (OFF_WRES + 24 * 65536)
__device__ float g_Wt[OFF_WO + 8 * 16384];      // ~19.7 MB

// ---------------- packed f32x2 helpers ----------------
#define FFMA2(acc, a, b) \
    asm("fma.rn.f32x2 %0, %1, %2, %0;" : "+l"(acc) : "l"(a), "l"(b))
#define PACK2(out, lo, hi) \
    asm("mov.b64 %0, {%1, %2};" : "=l"(out) : "r"(__float_as_uint(lo)), "r"(__float_as_uint(hi)))
#define UNPACK2(lo, hi, in) \
    { unsigned int _ulo, _uhi; \
      asm("mov.b64 {%0, %1}, %2;" : "=r"(_ulo), "=r"(_uhi) : "l"(in)); \
      lo = __uint_as_float(_ulo); hi = __uint_as_float(_uhi); }

// ---------------- cp.async ----------------
__device__ __forceinline__ uint32_t smem_u32(const void* p) {
    uint32_t a;
    asm("{ .reg .u64 t; cvta.to.shared.u64 t, %1; cvt.u32.u64 %0, t; }" : "=r"(a) : "l"(p));
    return a;
}
#define CP16(dst, src)  asm volatile("cp.async.cg.shared.global [%0], [%1], 16;" :: "r"(dst), "l"(src))
#define CPCOMMIT()      asm volatile("cp.async.commit_group;")
#define CPWAIT1()       asm volatile("cp.async.wait_group 1;")
#define CPWAIT0()       asm volatile("cp.async.wait_group 0;")

// ---------------- helpers ----------------
__device__ __forceinline__ void block_reduce2(float& s, float& q, float* shs, float* shq) {
    int tid = threadIdx.x;
    shs[tid] = s; shq[tid] = q;
    __syncthreads();
    for (int st = 128; st > 0; st >>= 1) {
        if (tid < st) { shs[tid] += shs[tid + st]; shq[tid] += shq[tid + st]; }
        __syncthreads();
    }
    s = shs[0]; q = shq[0];
}

// deterministic stats from fixed-slot partials; every block recomputes identically
__device__ __forceinline__ void stats_from_part(int b, int pcount, float denom,
                                                float& mean, float& rstd,
                                                float* shs, float* shq) {
    float s = 0.f, q = 0.f;
    for (int j = threadIdx.x; j < pcount; j += 256) {
        s += g_part[(b * 512 + j) * 2 + 0];
        q += g_part[(b * 512 + j) * 2 + 1];
    }
    block_reduce2(s, q, shs, shq);
    mean = s / denom;
    float var = fmaxf(q / denom - mean * mean, 0.f);
    rstd = rsqrtf(var + EPSV);
}

__global__ void k_zero(float* __restrict__ p, int n4) {
    int i = blockIdx.x * blockDim.x + threadIdx.x;
    if (i < n4) reinterpret_cast<float4*>(p)[i] = make_float4(0.f, 0.f, 0.f, 0.f);
}

// transpose weights: src [Mtot][Ktot] -> g_Wt[dstOff + (mt*Ktot + k)*128 + ml]
__global__ void k_wt(const float* __restrict__ src, int Ktot, size_t dstOff) {
    __shared__ float t[32][33];
    int k0 = blockIdx.x * 32, m0 = blockIdx.y * 32;
    int lx = threadIdx.x & 31, ly = threadIdx.x >> 5;
#pragma unroll
    for (int i = 0; i < 4; i++)
        t[ly + i * 8][lx] = src[(size_t)(m0 + ly + i * 8) * Ktot + k0 + lx];
    __syncthreads();
#pragma unroll
    for (int i = 0; i < 4; i++) {
        int k = k0 + ly + i * 8;
        int m = m0 + lx;
        g_Wt[dstOff + ((size_t)(m >> 7) * Ktot + k) * 128 + (m & 127)] = t[lx][ly + i * 8];
    }
}

// per-row stats for input x [b][c][t]
__global__ void k_rowstats(const float* __restrict__ X) {
    int c = blockIdx.x, b = blockIdx.y;
    const float* p = X + ((size_t)b * NCH + c) * TLEN;
    float s = 0.f, q = 0.f;
    for (int t = threadIdx.x; t < TLEN; t += 256) {
        float v = p[t];
        s += v; q += v * v;
    }
    __shared__ float shs[256], shq[256];
    block_reduce2(s, q, shs, shq);
    if (threadIdx.x == 0) {
        g_part[(b * 512 + c) * 2 + 0] = s;
        g_part[(b * 512 + c) * 2 + 1] = q;
    }
}

// fused gLN1 + depthwise dilated conv + PReLU + stats (reduces 100 h-partials itself)
__global__ void k_dw(const float* __restrict__ Wd, const float* __restrict__ bd,
                     const float* __restrict__ g1, const float* __restrict__ be1,
                     const float* __restrict__ a2, int layer, int dil, float denom) {
    __shared__ float shs[256], shq[256];
    int c = blockIdx.x, b = blockIdx.y;
    float mean, rstd;
    stats_from_part(b, 100, denom, mean, rstd, shs, shq);
    __syncthreads();
    int lc = layer * HID + c;
    float ga = g1[lc] * rstd;
    float dd = be1[lc] - ga * mean;
    float w0 = Wd[lc * 3 + 0], w1 = Wd[lc * 3 + 1], w2 = Wd[lc * 3 + 2];
    float bv = bd[lc];
    float al = a2[layer];
    const float* ph = g_h  + ((size_t)b * HID + c) * TLEN;
    float*       po = g_h2 + ((size_t)b * HID + c) * TLEN;
    float s = 0.f, q = 0.f;
    for (int t = threadIdx.x; t < TLEN; t += 256) {
        float ctr = ga * ph[t] + dd;
        float lf  = (t >= dil)        ? ga * ph[t - dil] + dd : 0.f;
        float rt  = (t + dil < TLEN)  ? ga * ph[t + dil] + dd : 0.f;
        float v = fmaf(w0, lf, fmaf(w1, ctr, fmaf(w2, rt, bv)));
        v = (v < 0.f) ? al * v : v;
        po[t] = v;
        s += v; q = fmaf(v, v, q);
    }
    block_reduce2(s, q, shs, shq);
    if (threadIdx.x == 0) {
        g_part[(b * 512 + c) * 2 + 0] = s;
        g_part[(b * 512 + c) * 2 + 1] = q;
    }
}

// ---------------- FFMA2 register core (8x8 tile as 8x4 packed pairs) ----------
struct GemmCore {
    unsigned long long acc2[8][4];
    __device__ __forceinline__ void init() {
#pragma unroll
        for (int r = 0; r < 8; r++)
#pragma unroll
            for (int c = 0; c < 4; c++) acc2[r][c] = 0ULL;
    }
    __device__ __forceinline__ void step(const float (*Wsm)[128], const float (*Xsm)[128],
                                         int tx, int ty) {
#pragma unroll
        for (int kk = 0; kk < 16; kk++) {
            const unsigned long long* Xp =
                reinterpret_cast<const unsigned long long*>(&Xsm[kk][tx * 8]);
            unsigned long long x2[4];
            x2[0] = Xp[0]; x2[1] = Xp[1]; x2[2] = Xp[2]; x2[3] = Xp[3];
            const float* Wp = &Wsm[kk][ty * 8];
#pragma unroll
            for (int r = 0; r < 8; r++) {
                float w = Wp[r];
                unsigned long long w2;
                PACK2(w2, w, w);
                FFMA2(acc2[r][0], w2, x2[0]);
                FFMA2(acc2[r][1], w2, x2[1]);
                FFMA2(acc2[r][2], w2, x2[2]);
                FFMA2(acc2[r][3], w2, x2[3]);
            }
        }
    }
    __device__ __forceinline__ void row(int r, float* out8) const {
#pragma unroll
        for (int c = 0; c < 4; c++) { UNPACK2(out8[2 * c], out8[2 * c + 1], acc2[r][c]); }
    }
};

// staging helpers -------------------------------------------------------------
// W tile for k-chunk: contiguous [16][128] copy from pre-transposed g_Wt
__device__ __forceinline__ void stageW(const float* __restrict__ src, float (*Wsm)[128]) {
#pragma unroll
    for (int e = 0; e < 2; e++) {
        int f = threadIdx.x + e * 256;       // 0..511
        int kk = f >> 5, mq = f & 31;
        uint32_t d = smem_u32(&Wsm[kk][mq * 4]);
        CP16(d, src + (size_t)kk * 128 + mq * 4);
    }
}
// X tile raw (INMODE 0): contiguous along t
__device__ __forceinline__ void stageX_async(const float* __restrict__ Xb, int k0, int n0,
                                             float (*Xsm)[128]) {
#pragma unroll
    for (int e = 0; e < 2; e++) {
        int f = threadIdx.x + e * 256;
        int c4 = f & 31, kk = f >> 5;
        uint32_t d = smem_u32(&Xsm[kk][c4 * 4]);
        CP16(d, Xb + (size_t)(k0 + kk) * TLEN + n0 + c4 * 4);
    }
}

// ---------------- pipelined fused pointwise GEMM ----------------
// D[b, m-tile by, n0..] = W . X + bias, OutOp.
// INMODE: 0 = raw (cp.async X), 1 = gLN-on-load, 2 = PReLU-on-load
// OUTMODE: 0 = store, 1 = add, 2 = PReLU+store+stats, 3 = sigmoid+store
// STATSIN: reduce g_part[pcount] at start for (mean,rstd)
template<int INMODE, int OUTMODE, int STATSIN>
__global__ __launch_bounds__(256, 2)
void k_gemm(const float* __restrict__ Xin, size_t wtOff,
            const float* __restrict__ bias, float* __restrict__ Out,
            int Ktot, int Mtot,
            const float* __restrict__ gvec, const float* __restrict__ bvec,
            const float* __restrict__ aprelu, int pcount, float denom) {
    __shared__ float Wsm[3][16][128];
    __shared__ float Xsm[3][16][128];
    int tid = threadIdx.x;
    int tx = tid & 15, ty = tid >> 4;
    int n0 = blockIdx.x * 128;
    int by = blockIdx.y;
    int b  = blockIdx.z;
    const float* Xb = Xin + (size_t)b * Ktot * TLEN;
    const float* wbase = g_Wt + wtOff + (size_t)by * Ktot * 128;

    float mean = 0.f, rstd = 0.f, aval = 0.f;
    if (INMODE == 1) {
        stats_from_part(b, pcount, denom, mean, rstd, &Xsm[0][0][0], &Xsm[0][2][0]);
        __syncthreads();
    }
    if (INMODE == 2 || OUTMODE == 2) { aval = *aprelu; }

    GemmCore core;
    core.init();
    const int NIT = Ktot / 16;

    float4 xr0, xr1;
    float ac0 = 0.f, dc0 = 0.f, ac1 = 0.f, dc1 = 0.f;

    // register-path X helpers (INMODE 1/2)
    auto ldgX = [&](int it) {
        int f0 = tid, f1 = tid + 256;
        int kg0 = it * 16 + (f0 >> 5), kg1 = it * 16 + (f1 >> 5);
        xr0 = *reinterpret_cast<const float4*>(&Xb[(size_t)kg0 * TLEN + n0 + (f0 & 31) * 4]);
        xr1 = *reinterpret_cast<const float4*>(&Xb[(size_t)kg1 * TLEN + n0 + (f1 & 31) * 4]);
        if (INMODE == 1) {
            ac0 = gvec[kg0] * rstd; dc0 = bvec[kg0] - ac0 * mean;
            ac1 = gvec[kg1] * rstd; dc1 = bvec[kg1] - ac1 * mean;
        }
    };
    auto stsX = [&](float (*Xs)[128]) {
        float4 v0 = xr0, v1 = xr1;
        if (INMODE == 1) {
            v0.x = fmaf(ac0, v0.x, dc0); v0.y = fmaf(ac0, v0.y, dc0);
            v0.z = fmaf(ac0, v0.z, dc0); v0.w = fmaf(ac0, v0.w, dc0);
            v1.x = fmaf(ac1, v1.x, dc1); v1.y = fmaf(ac1, v1.y, dc1);
            v1.z = fmaf(ac1, v1.z, dc1); v1.w = fmaf(ac1, v1.w, dc1);
        } else if (INMODE == 2) {
            v0.x = (v0.x < 0.f) ? v0.x * aval : v0.x; v0.y = (v0.y < 0.f) ? v0.y * aval : v0.y;
            v0.z = (v0.z < 0.f) ? v0.z * aval : v0.z; v0.w = (v0.w < 0.f) ? v0.w * aval : v0.w;
            v1.x = (v1.x < 0.f) ? v1.x * aval : v1.x; v1.y = (v1.y < 0.f) ? v1.y * aval : v1.y;
            v1.z = (v1.z < 0.f) ? v1.z * aval : v1.z; v1.w = (v1.w < 0.f) ? v1.w * aval : v1.w;
        }
        int f0 = tid, f1 = tid + 256;
        *reinterpret_cast<float4*>(&Xs[f0 >> 5][(f0 & 31) * 4]) = v0;
        *reinterpret_cast<float4*>(&Xs[f1 >> 5][(f1 & 31) * 4]) = v1;
    };

    // prologue: stage tiles 0 and 1
    if (INMODE == 0) {
        stageW(wbase, Wsm[0]); stageX_async(Xb, 0, n0, Xsm[0]); CPCOMMIT();
        stageW(wbase + (size_t)16 * 128, Wsm[1]); stageX_async(Xb, 16, n0, Xsm[1]); CPCOMMIT();
    } else {
        ldgX(0); stageW(wbase, Wsm[0]); CPCOMMIT(); stsX(Xsm[0]);
        ldgX(1); stageW(wbase + (size_t)16 * 128, Wsm[1]); CPCOMMIT(); stsX(Xsm[1]);
    }

    for (int i = 0; i < NIT; i++) {
        CPWAIT1();
        __syncthreads();
        bool more = (i + 2) < NIT;
        int nb = (i + 2) % 3;
        if (more) {
            stageW(wbase + (size_t)(i + 2) * 16 * 128, Wsm[nb]);
            if (INMODE == 0) stageX_async(Xb, (i + 2) * 16, n0, Xsm[nb]);
            else             ldgX(i + 2);
        }
        CPCOMMIT();
        core.step(Wsm[i % 3], Xsm[i % 3], tx, ty);
        if (more && INMODE != 0) stsX(Xsm[nb]);
    }

    // epilogue
    int m0 = by * 128;
    float ls = 0.f, lq = 0.f;
#pragma unroll
    for (int r = 0; r < 8; r++) {
        int o = m0 + ty * 8 + r;
        float bv = bias[o];
        float a8[8];
        core.row(r, a8);
        float* po = Out + ((size_t)b * Mtot + o) * TLEN + n0 + tx * 8;
#pragma unroll
        for (int h = 0; h < 2; h++) {
            float4 v;
            v.x = a8[h * 4 + 0] + bv;
            v.y = a8[h * 4 + 1] + bv;
            v.z = a8[h * 4 + 2] + bv;
            v.w = a8[h * 4 + 3] + bv;
            if (OUTMODE == 1) {
                float4 old = *reinterpret_cast<const float4*>(&po[h * 4]);
                v.x += old.x; v.y += old.y; v.z += old.z; v.w += old.w;
            } else if (OUTMODE == 2) {
                v.x = (v.x < 0.f) ? v.x * aval : v.x;
                v.y = (v.y < 0.f) ? v.y * aval : v.y;
                v.z = (v.z < 0.f) ? v.z * aval : v.z;
                v.w = (v.w < 0.f) ? v.w * aval : v.w;
                ls += v.x + v.y + v.z + v.w;
                lq = fmaf(v.x, v.x, lq); lq = fmaf(v.y, v.y, lq);
                lq = fmaf(v.z, v.z, lq); lq = fmaf(v.w, v.w, lq);
            } else if (OUTMODE == 3) {
                v.x = 1.f / (1.f + __expf(-v.x));
                v.y = 1.f / (1.f + __expf(-v.y));
                v.z = 1.f / (1.f + __expf(-v.z));
                v.w = 1.f / (1.f + __expf(-v.w));
            }
            *reinterpret_cast<float4*>(&po[h * 4]) = v;
        }
    }
    if (OUTMODE == 2) {
        __syncthreads();   // buffers free for reduce scratch
        float* shs = &Wsm[0][0][0];
        float* shq = &Wsm[0][2][0];
        block_reduce2(ls, lq, shs, shq);
        if (tid == 0) {
            int pid = by * gridDim.x + blockIdx.x;   // < 100
            g_part[(b * 512 + pid) * 2 + 0] = ls;
            g_part[(b * 512 + pid) * 2 + 1] = lq;
        }
    }
    CPWAIT0();
}

// ---------------- dual-output pipelined GEMM: skip + residual -----------------
// by=0 -> skip (offSk), by=1 -> residual (offRes); both add-mode, gLN-on-load.
__global__ __launch_bounds__(256, 2)
void k_gemm_dual(size_t offSk, size_t offRes,
                 const float* __restrict__ biasSk, const float* __restrict__ biasRes,
                 const float* __restrict__ gvec, const float* __restrict__ bvec,
                 float denom) {
    __shared__ float Wsm[3][16][128];
    __shared__ float Xsm[3][16][128];
    const int Ktot = HID;
    int tid = threadIdx.x;
    int tx = tid & 15, ty = tid >> 4;
    int n0 = blockIdx.x * 128;
    int by = blockIdx.y;
    int b  = blockIdx.z;
    const float* Xb = g_h2 + (size_t)b * Ktot * TLEN;
    const float* wbase = g_Wt + (by == 0 ? offSk : offRes);
    const float* bias  = (by == 0) ? biasSk : biasRes;
    float* Out = (by == 0) ? (g_skip + (size_t)b * BFT * TLEN)
                           : (g_feats + (size_t)b * BFT * TLEN);

    float mean, rstd;
    stats_from_part(b, 512, denom, mean, rstd, &Xsm[0][0][0], &Xsm[0][2][0]);
    __syncthreads();

    GemmCore core;
    core.init();
    const int NIT = Ktot / 16;

    float4 xr0, xr1;
    float ac0, dc0, ac1, dc1;
    auto ldgX = [&](int it) {
        int f0 = tid, f1 = tid + 256;
        int kg0 = it * 16 + (f0 >> 5), kg1 = it * 16 + (f1 >> 5);
        xr0 = *reinterpret_cast<const float4*>(&Xb[(size_t)kg0 * TLEN + n0 + (f0 & 31) * 4]);
        xr1 = *reinterpret_cast<const float4*>(&Xb[(size_t)kg1 * TLEN + n0 + (f1 & 31) * 4]);
        ac0 = gvec[kg0] * rstd; dc0 = bvec[kg0] - ac0 * mean;
        ac1 = gvec[kg1] * rstd; dc1 = bvec[kg1] - ac1 * mean;
    };
    auto stsX = [&](float (*Xs)[128]) {
        float4 v0 = xr0, v1 = xr1;
        v0.x = fmaf(ac0, v0.x, dc0); v0.y = fmaf(ac0, v0.y, dc0);
        v0.z = fmaf(ac0, v0.z, dc0); v0.w = fmaf(ac0, v0.w, dc0);
        v1.x = fmaf(ac1, v1.x, dc1); v1.y = fmaf(ac1, v1.y, dc1);
        v1.z = fmaf(ac1, v1.z, dc1); v1.w = fmaf(ac1, v1.w, dc1);
        int f0 = tid, f1 = tid + 256;
        *reinterpret_cast<float4*>(&Xs[f0 >> 5][(f0 & 31) * 4]) = v0;
        *reinterpret_cast<float4*>(&Xs[f1 >> 5][(f1 & 31) * 4]) = v1;
    };

    ldgX(0); stageW(wbase, Wsm[0]); CPCOMMIT(); stsX(Xsm[0]);
    ldgX(1); stageW(wbase + (size_t)16 * 128, Wsm[1]); CPCOMMIT(); stsX(Xsm[1]);

    for (int i = 0; i < NIT; i++) {
        CPWAIT1();
        __syncthreads();
        bool more = (i + 2) < NIT;
        int nb = (i + 2) % 3;
        if (more) {
            stageW(wbase + (size_t)(i + 2) * 16 * 128, Wsm[nb]);
            ldgX(i + 2);
        }
        CPCOMMIT();
        core.step(Wsm[i % 3], Xsm[i % 3], tx, ty);
        if (more) stsX(Xsm[nb]);
    }

#pragma unroll
    for (int r = 0; r < 8; r++) {
        int o = ty * 8 + r;
        float bv = bias[o];
        float a8[8];
        core.row(r, a8);
        float* po = Out + (size_t)o * TLEN + n0 + tx * 8;
#pragma unroll
        for (int h = 0; h < 2; h++) {
            float4 old = *reinterpret_cast<const float4*>(&po[h * 4]);
            float4 v;
            v.x = a8[h * 4 + 0] + bv + old.x;
            v.y = a8[h * 4 + 1] + bv + old.y;
            v.z = a8[h * 4 + 2] + bv + old.z;
            v.w = a8[h * 4 + 3] + bv + old.w;
            *reinterpret_cast<float4*>(&po[h * 4]) = v;
        }
    }
    CPWAIT0();
}

// ---------------- host launch ----------------
extern "C" void kernel_launch(void* const* d_in, const int* in_sizes, int n_in,
                              void* d_out, int out_size) {
    const float* x    = (const float*)d_in[0];
    const float* in_g = (const float*)d_in[1];
    const float* in_b = (const float*)d_in[2];
    const float* Wc   = (const float*)d_in[3];
    const float* bc   = (const float*)d_in[4];
    const float* W1   = (const float*)d_in[5];
    const float* b1   = (const float*)d_in[6];
    const float* a1   = (const float*)d_in[7];
    const float* g1   = (const float*)d_in[8];
    const float* be1  = (const float*)d_in[9];
    const float* Wd   = (const float*)d_in[10];
    const float* bd   = (const float*)d_in[11];
    const float* a2   = (const float*)d_in[12];
    const float* g2   = (const float*)d_in[13];
    const float* be2  = (const float*)d_in[14];
    const float* Wres = (const float*)d_in[15];
    const float* bres = (const float*)d_in[16];
    const float* Wsk  = (const float*)d_in[17];
    const float* bsk  = (const float*)d_in[18];
    const float* aout = (const float*)d_in[19];
    const float* Wo   = (const float*)d_in[20];
    const float* bo   = (const float*)d_in[21];
    float* out = (float*)d_out;

    float *p_feats, *p_skip;
    cudaGetSymbolAddress((void**)&p_feats, g_feats);
    cudaGetSymbolAddress((void**)&p_skip,  g_skip);

    const float denomN = (float)((size_t)NCH * TLEN);
    const float denomH = (float)((size_t)HID * TLEN);

    // weight transposes into tile layout [mt][k][ml]
    k_wt<<<dim3(16, 4),   256>>>(Wc,   512, (size_t)OFF_WC);
    k_wt<<<dim3(4, 384),  256>>>(W1,   128, (size_t)OFF_W1);
    k_wt<<<dim3(16, 96),  256>>>(Wsk,  512, (size_t)OFF_WSK);
    k_wt<<<dim3(16, 96),  256>>>(Wres, 512, (size_t)OFF_WRES);
    k_wt<<<dim3(4, 32),   256>>>(Wo,   128, (size_t)OFF_WO);

    // zero skip accumulator; input gLN stats
    {
        int n4 = BATCH * BFT * TLEN / 4;
        k_zero<<<(n4 + 255) / 256, 256>>>(p_skip, n4);
    }
    k_rowstats<<<dim3(NCH, BATCH), 256>>>(x);

    // feats = Wc @ gln(x) + bc  (K=512, stats reduced in-kernel from 512 partials)
    k_gemm<1, 0, 1><<<dim3(25, 1, BATCH), 256>>>(
        x, (size_t)OFF_WC, bc, p_feats, NCH, BFT, in_g, in_b, nullptr, 512, denomN);

    for (int i = 0; i < LAY; i++) {
        int dil = 1 << (i & 7);
        // h = prelu(W1 @ feats + b1) + stats partials (100)
        {
            float* dst;
            cudaGetSymbolAddress((void**)&dst, g_h);
            k_gemm<0, 2, 0><<<dim3(25, 4, BATCH), 256>>>(
                p_feats, (size_t)(OFF_W1 + (size_t)i * 65536), b1 + (size_t)i * HID, dst,
                BFT, HID, nullptr, nullptr, a1 + i, 0, 0.f);
        }
        // h2 = prelu(dwconv(gln1(h))) + stats partials (512)
        k_dw<<<dim3(HID, BATCH), 256>>>(Wd, bd, g1, be1, a2, i, dil, denomH);
        // skip (+ residual when not last), gln2-on-load, stats from 512 partials
        int ny = (i < LAY - 1) ? 2 : 1;
        k_gemm_dual<<<dim3(25, ny, BATCH), 256>>>(
            (size_t)(OFF_WSK + (size_t)i * 65536), (size_t)(OFF_WRES + (size_t)i * 65536),
            bsk + (size_t)i * BFT, bres + (size_t)i * BFT,
            g2 + (size_t)i * HID, be2 + (size_t)i * HID, denomH);
    }

    // out = sigmoid(Wo @ prelu(skip) + bo)
    k_gemm<2, 3, 0><<<dim3(25, 8, BATCH), 256>>>(
        p_skip, (size_t)OFF_WO, bo, out, BFT, NSRC * NCH,
        nullptr, nullptr, aout, 0, 0.f);
}

// round 17
// speedup vs baseline: 1.3055x; 1.0209x over previous
#include <cuda_runtime.h>
#include <cuda_bf16.h>
#include <math.h>
#include <stdint.h>

#define BATCH 8
#define NCH   512     // encoder feats
#define BFT   128     // bottleneck
#define HID   512     // hidden
#define TLEN  3200
#define LAY   24
#define NSRC  2
#define EPSV  1e-8f

// ---------------- scratch (device globals; no allocs allowed) ----------------
__device__ float          g_feats[BATCH * BFT * TLEN];   // [b][c][t] f32
__device__ float          g_h    [BATCH * HID * TLEN];   // f32 (52.4 MB)
__device__ __nv_bfloat16  g_h2   [BATCH * HID * TLEN];   // bf16 (26.2 MB)
__device__ float          g_skip [BATCH * BFT * TLEN];   // f32
__device__ float          g_part [BATCH * 512 * 2];      // fixed-slot partials

// transposed weights: per 128-row m-tile, layout [mt][k][ml], ml in 0..127
#define OFF_WC   0
#define OFF_W1   65536
#define OFF_WSK  (OFF_W1  + 24 * 65536)
#define OFF_WRES (OFF_WSK + 24 * 65536)
#define OFF_WO   (OFF_WRES + 24 * 65536)
__device__ float g_Wt[OFF_WO + 8 * 16384];

// ---------------- packed f32x2 helpers ----------------
#define FFMA2(acc, a, b) \
    asm("fma.rn.f32x2 %0, %1, %2, %0;" : "+l"(acc) : "l"(a), "l"(b))
#define PACK2(out, lo, hi) \
    asm("mov.b64 %0, {%1, %2};" : "=l"(out) : "r"(__float_as_uint(lo)), "r"(__float_as_uint(hi)))
#define UNPACK2(lo, hi, in) \
    { unsigned int _ulo, _uhi; \
      asm("mov.b64 {%0, %1}, %2;" : "=r"(_ulo), "=r"(_uhi) : "l"(in)); \
      lo = __uint_as_float(_ulo); hi = __uint_as_float(_uhi); }

// ---------------- cp.async ----------------
__device__ __forceinline__ uint32_t smem_u32(const void* p) {
    uint32_t a;
    asm("{ .reg .u64 t; cvta.to.shared.u64 t, %1; cvt.u32.u64 %0, t; }" : "=r"(a) : "l"(p));
    return a;
}
#define CP16(dst, src)  asm volatile("cp.async.cg.shared.global [%0], [%1], 16;" :: "r"(dst), "l"(src))
#define CPCOMMIT()      asm volatile("cp.async.commit_group;")
#define CPWAIT1()       asm volatile("cp.async.wait_group 1;")
#define CPWAIT0()       asm volatile("cp.async.wait_group 0;")

// ---------------- helpers ----------------
__device__ __forceinline__ void block_reduce2(float& s, float& q, float* shs, float* shq) {
    int tid = threadIdx.x;
    shs[tid] = s; shq[tid] = q;
    __syncthreads();
    for (int st = 128; st > 0; st >>= 1) {
        if (tid < st) { shs[tid] += shs[tid + st]; shq[tid] += shq[tid + st]; }
        __syncthreads();
    }
    s = shs[0]; q = shq[0];
}

__device__ __forceinline__ void stats_from_part(int b, int pcount, float denom,
                                                float& mean, float& rstd,
                                                float* shs, float* shq) {
    float s = 0.f, q = 0.f;
    for (int j = threadIdx.x; j < pcount; j += 256) {
        s += g_part[(b * 512 + j) * 2 + 0];
        q += g_part[(b * 512 + j) * 2 + 1];
    }
    block_reduce2(s, q, shs, shq);
    mean = s / denom;
    float var = fmaxf(q / denom - mean * mean, 0.f);
    rstd = rsqrtf(var + EPSV);
}

// load 4 consecutive bf16 as float4 (8B load)
__device__ __forceinline__ float4 ldbf4(const __nv_bfloat16* p) {
    uint2 u = *reinterpret_cast<const uint2*>(p);
    __nv_bfloat162 a = *reinterpret_cast<__nv_bfloat162*>(&u.x);
    __nv_bfloat162 bb = *reinterpret_cast<__nv_bfloat162*>(&u.y);
    float2 fa = __bfloat1622float2(a), fb = __bfloat1622float2(bb);
    return make_float4(fa.x, fa.y, fb.x, fb.y);
}

__global__ void k_zero(float* __restrict__ p, int n4) {
    int i = blockIdx.x * blockDim.x + threadIdx.x;
    if (i < n4) reinterpret_cast<float4*>(p)[i] = make_float4(0.f, 0.f, 0.f, 0.f);
}

// transpose weights: src [Mtot][Ktot] -> g_Wt[dstOff + (mt*Ktot + k)*128 + ml]
__global__ void k_wt(const float* __restrict__ src, int Ktot, size_t dstOff) {
    __shared__ float t[32][33];
    int k0 = blockIdx.x * 32, m0 = blockIdx.y * 32;
    int lx = threadIdx.x & 31, ly = threadIdx.x >> 5;
#pragma unroll
    for (int i = 0; i < 4; i++)
        t[ly + i * 8][lx] = src[(size_t)(m0 + ly + i * 8) * Ktot + k0 + lx];
    __syncthreads();
#pragma unroll
    for (int i = 0; i < 4; i++) {
        int k = k0 + ly + i * 8;
        int m = m0 + lx;
        g_Wt[dstOff + ((size_t)(m >> 7) * Ktot + k) * 128 + (m & 127)] = t[lx][ly + i * 8];
    }
}

// per-row stats for input x [b][c][t]
__global__ void k_rowstats(const float* __restrict__ X) {
    int c = blockIdx.x, b = blockIdx.y;
    const float* p = X + ((size_t)b * NCH + c) * TLEN;
    float s = 0.f, q = 0.f;
    for (int t = threadIdx.x; t < TLEN; t += 256) {
        float v = p[t];
        s += v; q += v * v;
    }
    __shared__ float shs[256], shq[256];
    block_reduce2(s, q, shs, shq);
    if (threadIdx.x == 0) {
        g_part[(b * 512 + c) * 2 + 0] = s;
        g_part[(b * 512 + c) * 2 + 1] = q;
    }
}

// fused gLN1 + depthwise dilated conv + PReLU + stats; h f32 in, h2 bf16 out
__global__ void k_dw(const float* __restrict__ Wd, const float* __restrict__ bd,
                     const float* __restrict__ g1, const float* __restrict__ be1,
                     const float* __restrict__ a2, int layer, int dil, float denom) {
    __shared__ float shs[256], shq[256];
    int c = blockIdx.x, b = blockIdx.y;
    float mean, rstd;
    stats_from_part(b, 100, denom, mean, rstd, shs, shq);
    __syncthreads();
    int lc = layer * HID + c;
    float ga = g1[lc] * rstd;
    float dd = be1[lc] - ga * mean;
    float w0 = Wd[lc * 3 + 0], w1 = Wd[lc * 3 + 1], w2 = Wd[lc * 3 + 2];
    float bv = bd[lc];
    float al = a2[layer];
    const float*   ph = g_h  + ((size_t)b * HID + c) * TLEN;
    __nv_bfloat16* po = g_h2 + ((size_t)b * HID + c) * TLEN;
    float s = 0.f, q = 0.f;
    for (int t = threadIdx.x; t < TLEN; t += 256) {
        float ctr = fmaf(ga, ph[t], dd);
        float lf  = (t >= dil)        ? fmaf(ga, ph[t - dil], dd) : 0.f;
        float rt  = (t + dil < TLEN)  ? fmaf(ga, ph[t + dil], dd) : 0.f;
        float v = fmaf(w0, lf, fmaf(w1, ctr, fmaf(w2, rt, bv)));
        v = (v < 0.f) ? al * v : v;
        po[t] = __float2bfloat16(v);
        s += v; q = fmaf(v, v, q);
    }
    block_reduce2(s, q, shs, shq);
    if (threadIdx.x == 0) {
        g_part[(b * 512 + c) * 2 + 0] = s;
        g_part[(b * 512 + c) * 2 + 1] = q;
    }
}

// ---------------- FFMA2 register core (8x8 tile as 8x4 packed pairs) ----------
struct GemmCore {
    unsigned long long acc2[8][4];
    __device__ __forceinline__ void init() {
#pragma unroll
        for (int r = 0; r < 8; r++)
#pragma unroll
            for (int c = 0; c < 4; c++) acc2[r][c] = 0ULL;
    }
    __device__ __forceinline__ void step(const float (*Wsm)[128], const float (*Xsm)[128],
                                         int tx, int ty) {
#pragma unroll
        for (int kk = 0; kk < 16; kk++) {
            const unsigned long long* Xp =
                reinterpret_cast<const unsigned long long*>(&Xsm[kk][tx * 8]);
            unsigned long long x2[4];
            x2[0] = Xp[0]; x2[1] = Xp[1]; x2[2] = Xp[2]; x2[3] = Xp[3];
            const float* Wp = &Wsm[kk][ty * 8];
#pragma unroll
            for (int r = 0; r < 8; r++) {
                float w = Wp[r];
                unsigned long long w2;
                PACK2(w2, w, w);
                FFMA2(acc2[r][0], w2, x2[0]);
                FFMA2(acc2[r][1], w2, x2[1]);
                FFMA2(acc2[r][2], w2, x2[2]);
                FFMA2(acc2[r][3], w2, x2[3]);
            }
        }
    }
    __device__ __forceinline__ void row(int r, float* out8) const {
#pragma unroll
        for (int c = 0; c < 4; c++) { UNPACK2(out8[2 * c], out8[2 * c + 1], acc2[r][c]); }
    }
};

// staging helpers -------------------------------------------------------------
__device__ __forceinline__ void stageW(const float* __restrict__ src, float (*Wsm)[128]) {
#pragma unroll
    for (int e = 0; e < 2; e++) {
        int f = threadIdx.x + e * 256;       // 0..511
        int kk = f >> 5, mq = f & 31;
        uint32_t d = smem_u32(&Wsm[kk][mq * 4]);
        CP16(d, src + (size_t)kk * 128 + mq * 4);
    }
}
__device__ __forceinline__ void stageX_async(const float* __restrict__ Xb, int k0, int n0,
                                             float (*Xsm)[128]) {
#pragma unroll
    for (int e = 0; e < 2; e++) {
        int f = threadIdx.x + e * 256;
        int c4 = f & 31, kk = f >> 5;
        uint32_t d = smem_u32(&Xsm[kk][c4 * 4]);
        CP16(d, Xb + (size_t)(k0 + kk) * TLEN + n0 + c4 * 4);
    }
}

// ---------------- pipelined fused pointwise GEMM ----------------
// INMODE: 0 = raw f32 (cp.async X), 1 = gLN-on-load, 2 = PReLU-on-load
// OUTMODE: 0 = store, 1 = add, 2 = PReLU+store+stats, 3 = sigmoid+store
template<int INMODE, int OUTMODE, int STATSIN>
__global__ __launch_bounds__(256, 2)
void k_gemm(const float* __restrict__ Xin, size_t wtOff,
            const float* __restrict__ bias, float* __restrict__ Out,
            int Ktot, int Mtot,
            const float* __restrict__ gvec, const float* __restrict__ bvec,
            const float* __restrict__ aprelu, int pcount, float denom) {
    __shared__ float Wsm[3][16][128];
    __shared__ float Xsm[3][16][128];
    int tid = threadIdx.x;
    int tx = tid & 15, ty = tid >> 4;
    int n0 = blockIdx.x * 128;
    int by = blockIdx.y;
    int b  = blockIdx.z;
    const float* Xb = Xin + (size_t)b * Ktot * TLEN;
    const float* wbase = g_Wt + wtOff + (size_t)by * Ktot * 128;

    float mean = 0.f, rstd = 0.f, aval = 0.f;
    if (INMODE == 1) {
        stats_from_part(b, pcount, denom, mean, rstd, &Xsm[0][0][0], &Xsm[0][2][0]);
        __syncthreads();
    }
    if (INMODE == 2 || OUTMODE == 2) { aval = *aprelu; }

    GemmCore core;
    core.init();
    const int NIT = Ktot / 16;

    float4 xr0, xr1;
    float ac0 = 0.f, dc0 = 0.f, ac1 = 0.f, dc1 = 0.f;

    auto ldgX = [&](int it) {
        int f0 = tid, f1 = tid + 256;
        int kg0 = it * 16 + (f0 >> 5), kg1 = it * 16 + (f1 >> 5);
        xr0 = *reinterpret_cast<const float4*>(&Xb[(size_t)kg0 * TLEN + n0 + (f0 & 31) * 4]);
        xr1 = *reinterpret_cast<const float4*>(&Xb[(size_t)kg1 * TLEN + n0 + (f1 & 31) * 4]);
        if (INMODE == 1) {
            ac0 = gvec[kg0] * rstd; dc0 = bvec[kg0] - ac0 * mean;
            ac1 = gvec[kg1] * rstd; dc1 = bvec[kg1] - ac1 * mean;
        }
    };
    auto stsX = [&](float (*Xs)[128]) {
        float4 v0 = xr0, v1 = xr1;
        if (INMODE == 1) {
            v0.x = fmaf(ac0, v0.x, dc0); v0.y = fmaf(ac0, v0.y, dc0);
            v0.z = fmaf(ac0, v0.z, dc0); v0.w = fmaf(ac0, v0.w, dc0);
            v1.x = fmaf(ac1, v1.x, dc1); v1.y = fmaf(ac1, v1.y, dc1);
            v1.z = fmaf(ac1, v1.z, dc1); v1.w = fmaf(ac1, v1.w, dc1);
        } else if (INMODE == 2) {
            v0.x = (v0.x < 0.f) ? v0.x * aval : v0.x; v0.y = (v0.y < 0.f) ? v0.y * aval : v0.y;
            v0.z = (v0.z < 0.f) ? v0.z * aval : v0.z; v0.w = (v0.w < 0.f) ? v0.w * aval : v0.w;
            v1.x = (v1.x < 0.f) ? v1.x * aval : v1.x; v1.y = (v1.y < 0.f) ? v1.y * aval : v1.y;
            v1.z = (v1.z < 0.f) ? v1.z * aval : v1.z; v1.w = (v1.w < 0.f) ? v1.w * aval : v1.w;
        }
        int f0 = tid, f1 = tid + 256;
        *reinterpret_cast<float4*>(&Xs[f0 >> 5][(f0 & 31) * 4]) = v0;
        *reinterpret_cast<float4*>(&Xs[f1 >> 5][(f1 & 31) * 4]) = v1;
    };

    if (INMODE == 0) {
        stageW(wbase, Wsm[0]); stageX_async(Xb, 0, n0, Xsm[0]); CPCOMMIT();
        stageW(wbase + (size_t)16 * 128, Wsm[1]); stageX_async(Xb, 16, n0, Xsm[1]); CPCOMMIT();
    } else {
        ldgX(0); stageW(wbase, Wsm[0]); CPCOMMIT(); stsX(Xsm[0]);
        ldgX(1); stageW(wbase + (size_t)16 * 128, Wsm[1]); CPCOMMIT(); stsX(Xsm[1]);
    }

    for (int i = 0; i < NIT; i++) {
        CPWAIT1();
        __syncthreads();
        bool more = (i + 2) < NIT;
        int nb = (i + 2) % 3;
        if (more) {
            stageW(wbase + (size_t)(i + 2) * 16 * 128, Wsm[nb]);
            if (INMODE == 0) stageX_async(Xb, (i + 2) * 16, n0, Xsm[nb]);
            else             ldgX(i + 2);
        }
        CPCOMMIT();
        core.step(Wsm[i % 3], Xsm[i % 3], tx, ty);
        if (more && INMODE != 0) stsX(Xsm[nb]);
    }

    // epilogue
    int m0 = by * 128;
    float ls = 0.f, lq = 0.f;
#pragma unroll
    for (int r = 0; r < 8; r++) {
        int o = m0 + ty * 8 + r;
        float bv = bias[o];
        float a8[8];
        core.row(r, a8);
        float* po = Out + ((size_t)b * Mtot + o) * TLEN + n0 + tx * 8;
#pragma unroll
        for (int h = 0; h < 2; h++) {
            float4 v;
            v.x = a8[h * 4 + 0] + bv;
            v.y = a8[h * 4 + 1] + bv;
            v.z = a8[h * 4 + 2] + bv;
            v.w = a8[h * 4 + 3] + bv;
            if (OUTMODE == 1) {
                float4 old = *reinterpret_cast<const float4*>(&po[h * 4]);
                v.x += old.x; v.y += old.y; v.z += old.z; v.w += old.w;
            } else if (OUTMODE == 2) {
                v.x = (v.x < 0.f) ? v.x * aval : v.x;
                v.y = (v.y < 0.f) ? v.y * aval : v.y;
                v.z = (v.z < 0.f) ? v.z * aval : v.z;
                v.w = (v.w < 0.f) ? v.w * aval : v.w;
                ls += v.x + v.y + v.z + v.w;
                lq = fmaf(v.x, v.x, lq); lq = fmaf(v.y, v.y, lq);
                lq = fmaf(v.z, v.z, lq); lq = fmaf(v.w, v.w, lq);
            } else if (OUTMODE == 3) {
                v.x = 1.f / (1.f + __expf(-v.x));
                v.y = 1.f / (1.f + __expf(-v.y));
                v.z = 1.f / (1.f + __expf(-v.z));
                v.w = 1.f / (1.f + __expf(-v.w));
            }
            *reinterpret_cast<float4*>(&po[h * 4]) = v;
        }
    }
    if (OUTMODE == 2) {
        __syncthreads();
        float* shs = &Wsm[0][0][0];
        float* shq = &Wsm[0][2][0];
        block_reduce2(ls, lq, shs, shq);
        if (tid == 0) {
            int pid = by * gridDim.x + blockIdx.x;   // < 100
            g_part[(b * 512 + pid) * 2 + 0] = ls;
            g_part[(b * 512 + pid) * 2 + 1] = lq;
        }
    }
    CPWAIT0();
}

// ---------------- dual-output pipelined GEMM: skip + residual -----------------
// X = g_h2 (bf16), converted + gLN-affine during staging; outputs f32 add-mode.
__global__ __launch_bounds__(256, 2)
void k_gemm_dual(size_t offSk, size_t offRes,
                 const float* __restrict__ biasSk, const float* __restrict__ biasRes,
                 const float* __restrict__ gvec, const float* __restrict__ bvec,
                 float denom) {
    __shared__ float Wsm[3][16][128];
    __shared__ float Xsm[3][16][128];
    const int Ktot = HID;
    int tid = threadIdx.x;
    int tx = tid & 15, ty = tid >> 4;
    int n0 = blockIdx.x * 128;
    int by = blockIdx.y;
    int b  = blockIdx.z;
    const __nv_bfloat16* Xb = g_h2 + (size_t)b * Ktot * TLEN;
    const float* wbase = g_Wt + (by == 0 ? offSk : offRes);
    const float* bias  = (by == 0) ? biasSk : biasRes;
    float* Out = (by == 0) ? (g_skip + (size_t)b * BFT * TLEN)
                           : (g_feats + (size_t)b * BFT * TLEN);

    float mean, rstd;
    stats_from_part(b, 512, denom, mean, rstd, &Xsm[0][0][0], &Xsm[0][2][0]);
    __syncthreads();

    GemmCore core;
    core.init();
    const int NIT = Ktot / 16;

    float4 xr0, xr1;
    float ac0, dc0, ac1, dc1;
    auto ldgX = [&](int it) {
        int f0 = tid, f1 = tid + 256;
        int kg0 = it * 16 + (f0 >> 5), kg1 = it * 16 + (f1 >> 5);
        xr0 = ldbf4(&Xb[(size_t)kg0 * TLEN + n0 + (f0 & 31) * 4]);
        xr1 = ldbf4(&Xb[(size_t)kg1 * TLEN + n0 + (f1 & 31) * 4]);
        ac0 = gvec[kg0] * rstd; dc0 = bvec[kg0] - ac0 * mean;
        ac1 = gvec[kg1] * rstd; dc1 = bvec[kg1] - ac1 * mean;
    };
    auto stsX = [&](float (*Xs)[128]) {
        float4 v0 = xr0, v1 = xr1;
        v0.x = fmaf(ac0, v0.x, dc0); v0.y = fmaf(ac0, v0.y, dc0);
        v0.z = fmaf(ac0, v0.z, dc0); v0.w = fmaf(ac0, v0.w, dc0);
        v1.x = fmaf(ac1, v1.x, dc1); v1.y = fmaf(ac1, v1.y, dc1);
        v1.z = fmaf(ac1, v1.z, dc1); v1.w = fmaf(ac1, v1.w, dc1);
        int f0 = tid, f1 = tid + 256;
        *reinterpret_cast<float4*>(&Xs[f0 >> 5][(f0 & 31) * 4]) = v0;
        *reinterpret_cast<float4*>(&Xs[f1 >> 5][(f1 & 31) * 4]) = v1;
    };

    ldgX(0); stageW(wbase, Wsm[0]); CPCOMMIT(); stsX(Xsm[0]);
    ldgX(1); stageW(wbase + (size_t)16 * 128, Wsm[1]); CPCOMMIT(); stsX(Xsm[1]);

    for (int i = 0; i < NIT; i++) {
        CPWAIT1();
        __syncthreads();
        bool more = (i + 2) < NIT;
        int nb = (i + 2) % 3;
        if (more) {
            stageW(wbase + (size_t)(i + 2) * 16 * 128, Wsm[nb]);
            ldgX(i + 2);
        }
        CPCOMMIT();
        core.step(Wsm[i % 3], Xsm[i % 3], tx, ty);
        if (more) stsX(Xsm[nb]);
    }

#pragma unroll
    for (int r = 0; r < 8; r++) {
        int o = ty * 8 + r;
        float bv = bias[o];
        float a8[8];
        core.row(r, a8);
        float* po = Out + (size_t)o * TLEN + n0 + tx * 8;
#pragma unroll
        for (int h = 0; h < 2; h++) {
            float4 old = *reinterpret_cast<const float4*>(&po[h * 4]);
            float4 v;
            v.x = a8[h * 4 + 0] + bv + old.x;
            v.y = a8[h * 4 + 1] + bv + old.y;
            v.z = a8[h * 4 + 2] + bv + old.z;
            v.w = a8[h * 4 + 3] + bv + old.w;
            *reinterpret_cast<float4*>(&po[h * 4]) = v;
        }
    }
    CPWAIT0();
}

// ---------------- host launch ----------------
extern "C" void kernel_launch(void* const* d_in, const int* in_sizes, int n_in,
                              void* d_out, int out_size) {
    const float* x    = (const float*)d_in[0];
    const float* in_g = (const float*)d_in[1];
    const float* in_b = (const float*)d_in[2];
    const float* Wc   = (const float*)d_in[3];
    const float* bc   = (const float*)d_in[4];
    const float* W1   = (const float*)d_in[5];
    const float* b1   = (const float*)d_in[6];
    const float* a1   = (const float*)d_in[7];
    const float* g1   = (const float*)d_in[8];
    const float* be1  = (const float*)d_in[9];
    const float* Wd   = (const float*)d_in[10];
    const float* bd   = (const float*)d_in[11];
    const float* a2   = (const float*)d_in[12];
    const float* g2   = (const float*)d_in[13];
    const float* be2  = (const float*)d_in[14];
    const float* Wres = (const float*)d_in[15];
    const float* bres = (const float*)d_in[16];
    const float* Wsk  = (const float*)d_in[17];
    const float* bsk  = (const float*)d_in[18];
    const float* aout = (const float*)d_in[19];
    const float* Wo   = (const float*)d_in[20];
    const float* bo   = (const float*)d_in[21];
    float* out = (float*)d_out;

    float *p_feats, *p_skip, *p_h;
    cudaGetSymbolAddress((void**)&p_feats, g_feats);
    cudaGetSymbolAddress((void**)&p_skip,  g_skip);
    cudaGetSymbolAddress((void**)&p_h,     g_h);

    const float denomN = (float)((size_t)NCH * TLEN);
    const float denomH = (float)((size_t)HID * TLEN);

    // weight transposes into tile layout [mt][k][ml]
    k_wt<<<dim3(16, 4),   256>>>(Wc,   512, (size_t)OFF_WC);
    k_wt<<<dim3(4, 384),  256>>>(W1,   128, (size_t)OFF_W1);
    k_wt<<<dim3(16, 96),  256>>>(Wsk,  512, (size_t)OFF_WSK);
    k_wt<<<dim3(16, 96),  256>>>(Wres, 512, (size_t)OFF_WRES);
    k_wt<<<dim3(4, 32),   256>>>(Wo,   128, (size_t)OFF_WO);

    // zero skip accumulator; input gLN stats
    {
        int n4 = BATCH * BFT * TLEN / 4;
        k_zero<<<(n4 + 255) / 256, 256>>>(p_skip, n4);
    }
    k_rowstats<<<dim3(NCH, BATCH), 256>>>(x);

    // feats = Wc @ gln(x) + bc  (K=512; stats reduced in-kernel from 512 partials)
    k_gemm<1, 0, 1><<<dim3(25, 1, BATCH), 256>>>(
        x, (size_t)OFF_WC, bc, p_feats, NCH, BFT, in_g, in_b, nullptr, 512, denomN);

    for (int i = 0; i < LAY; i++) {
        int dil = 1 << (i & 7);
        // h = prelu(W1 @ feats + b1) + stats partials (100); h stays f32
        k_gemm<0, 2, 0><<<dim3(25, 4, BATCH), 256>>>(
            p_feats, (size_t)(OFF_W1 + (size_t)i * 65536), b1 + (size_t)i * HID, p_h,
            BFT, HID, nullptr, nullptr, a1 + i, 0, 0.f);
        // h2 = prelu(dwconv(gln1(h))) + stats partials (512); h2 stored bf16
        k_dw<<<dim3(HID, BATCH), 256>>>(Wd, bd, g1, be1, a2, i, dil, denomH);
        // skip (+ residual when not last), gln2-on-load from bf16 h2
        int ny = (i < LAY - 1) ? 2 : 1;
        k_gemm_dual<<<dim3(25, ny, BATCH), 256>>>(
            (size_t)(OFF_WSK + (size_t)i * 65536), (size_t)(OFF_WRES + (size_t)i * 65536),
            bsk + (size_t)i * BFT, bres + (size_t)i * BFT,
            g2 + (size_t)i * HID, be2 + (size_t)i * HID, denomH);
    }

    // out = sigmoid(Wo @ prelu(skip) + bo)
    k_gemm<2, 3, 0><<<dim3(25, 8, BATCH), 256>>>(
        p_skip, (size_t)OFF_WO, bo, out, BFT, NSRC * NCH,
        nullptr, nullptr, aout, 0, 0.f);
}